// round 6
// baseline (speedup 1.0000x reference)
#include <cuda_runtime.h>
#include <cuda_bf16.h>
#include <math.h>
#include <stdint.h>

// ---------------------------------------------------------------------------
// Problem constants
// ---------------------------------------------------------------------------
#define D_MODEL   1024
#define N_HEADS   16
#define N_KV      8
#define HEAD_DIM  64
#define HIDDEN    4096
#define BATCH     4
#define SEQ       2048
#define BT        (BATCH * SEQ)

// ---------------------------------------------------------------------------
// Scratch (device globals)
// ---------------------------------------------------------------------------
__device__ float g_h  [BT * D_MODEL];
__device__ float g_q  [BT * D_MODEL];
__device__ float g_k  [BT * N_KV * HEAD_DIM];
__device__ float g_v  [BT * N_KV * HEAD_DIM];
__device__ float g_ao [BT * D_MODEL];
__device__ float g_h2 [BT * D_MODEL];
__device__ float g_a  [BT * HIDDEN];
__device__ float g_b  [BT * HIDDEN];

__device__ float g_wqT[D_MODEL * D_MODEL];
__device__ float g_wkT[(N_KV * HEAD_DIM) * D_MODEL];
__device__ float g_wvT[(N_KV * HEAD_DIM) * D_MODEL];
__device__ float g_woT[D_MODEL * D_MODEL];
__device__ float g_w1T[HIDDEN * D_MODEL];
__device__ float g_w2T[HIDDEN * D_MODEL];
__device__ float g_w3T[D_MODEL * HIDDEN];

// ---------------------------------------------------------------------------
// Helpers
// ---------------------------------------------------------------------------
__device__ __forceinline__ uint32_t f2tf32(float x) {
    uint32_t r;
    asm("cvt.rna.tf32.f32 %0, %1;" : "=r"(r) : "f"(x));
    return r;
}

__device__ __forceinline__ void mma_tf32(float* c, const uint32_t* a, const uint32_t* b) {
    asm volatile(
        "mma.sync.aligned.m16n8k8.row.col.f32.tf32.tf32.f32 "
        "{%0,%1,%2,%3}, {%4,%5,%6,%7}, {%8,%9}, {%0,%1,%2,%3};\n"
        : "+f"(c[0]), "+f"(c[1]), "+f"(c[2]), "+f"(c[3])
        : "r"(a[0]), "r"(a[1]), "r"(a[2]), "r"(a[3]), "r"(b[0]), "r"(b[1]));
}

__device__ __forceinline__ void ldm_x4(uint32_t* d, uint32_t saddr) {
    asm volatile(
        "ldmatrix.sync.aligned.m8n8.x4.shared.b16 {%0,%1,%2,%3}, [%4];"
        : "=r"(d[0]), "=r"(d[1]), "=r"(d[2]), "=r"(d[3]) : "r"(saddr));
}

__device__ __forceinline__ uint32_t cvta_s(const void* p) {
    return (uint32_t)__cvta_generic_to_shared(p);
}
__device__ __forceinline__ void cp16(uint32_t dst, const void* src) {
    asm volatile(
        "{ .reg .u64 g; cvta.to.global.u64 g, %1; "
        "cp.async.cg.shared.global [%0], [g], 16; }"
        :: "r"(dst), "l"(src) : "memory");
}
#define CP_COMMIT() asm volatile("cp.async.commit_group;\n" ::: "memory")
#define CP_WAIT1()  asm volatile("cp.async.wait_group 1;\n" ::: "memory")
#define CP_WAIT0()  asm volatile("cp.async.wait_group 0;\n" ::: "memory")

// ---------------------------------------------------------------------------
// tf32 tensor-core GEMM: C[M,N] = A[M,K] @ Bt[N,K]^T
// epi: 0 none | 1 C = acc + R | 2 C = silu(R) * acc
// CTA 128 threads, 2x2 warps, warp tile 64x64, BK=32, 2-stage cp.async,
// ldmatrix.x4 fragment loads, raw fp32 operands (tf32 truncation in MMA).
// ---------------------------------------------------------------------------
#define BKC   32
#define LDP   36
#define STG_F (128 * LDP)
#define GEMM_SMEM_BYTES (4 * STG_F * 4)

__global__ void __launch_bounds__(128, 2)
tc_gemm(const float* __restrict__ A, const float* __restrict__ Bt,
        const float* __restrict__ R, float* __restrict__ C,
        int M, int N, int K, int epi) {
    extern __shared__ float sm[];
    float* Abuf[2] = { sm,             sm + 2 * STG_F };
    float* Bbuf[2] = { sm + STG_F,     sm + 3 * STG_F };

    const int tid  = threadIdx.x;
    const int wid  = tid >> 5;
    const int lane = tid & 31;
    const int wm   = wid >> 1;
    const int wn   = wid & 1;
    const int gr   = lane >> 2;
    const int gc   = lane & 3;
    const int m0 = blockIdx.y << 7;
    const int n0 = blockIdx.x << 7;

    const int lr  = tid >> 2;
    const int lc8 = (tid & 3) << 3;

    const float* Ag = A  + (long)(m0 + lr) * K + lc8;
    const float* Bg = Bt + (long)(n0 + lr) * K + lc8;

    uint32_t sAbase[2], sBbase[2];
    uint32_t sA[2], sB[2];
    #pragma unroll
    for (int s = 0; s < 2; s++) {
        sAbase[s] = cvta_s(Abuf[s]);
        sBbase[s] = cvta_s(Bbuf[s]);
        sA[s] = cvta_s(&Abuf[s][lr * LDP + lc8]);
        sB[s] = cvta_s(&Bbuf[s][lr * LDP + lc8]);
    }
    const uint32_t rowstep = 32 * LDP * 4;

    // ldmatrix per-lane offsets (bytes)
    const int l7  = lane & 7;
    const int q1  = (lane >> 3) & 1;
    const int q2  = lane >> 4;
    // A: quad0 rows0-7/k-lo, quad1 rows8-15/k-lo, quad2 rows0-7/k-hi, quad3 rows8-15/k-hi
    const uint32_t aOff = (uint32_t)(((wm * 64 + l7 + q1 * 8) * LDP + q2 * 4) * 4);
    // B: quad0 nt rows/k-lo, quad1 nt rows/k-hi, quad2 nt+1 rows/k-lo, quad3 nt+1/k-hi
    const uint32_t bOff = (uint32_t)(((wn * 64 + l7 + q2 * 8) * LDP + q1 * 4) * 4);

    const int NC = K / BKC;

    float acc[4][8][4];
    #pragma unroll
    for (int i = 0; i < 4; i++)
        #pragma unroll
        for (int j = 0; j < 8; j++)
            #pragma unroll
            for (int q = 0; q < 4; q++) acc[i][j][q] = 0.f;

    // issue chunk 0
    {
        #pragma unroll
        for (int p = 0; p < 4; p++) {
            cp16(sA[0] + p * rowstep,      Ag + (long)(p * 32) * K);
            cp16(sA[0] + p * rowstep + 16, Ag + (long)(p * 32) * K + 4);
            cp16(sB[0] + p * rowstep,      Bg + (long)(p * 32) * K);
            cp16(sB[0] + p * rowstep + 16, Bg + (long)(p * 32) * K + 4);
        }
        CP_COMMIT();
    }

    for (int i = 0; i < NC; i++) {
        const int cur = i & 1;
        if (i + 1 < NC) {
            const int nxt = cur ^ 1;
            const long ko = (long)(i + 1) * BKC;
            #pragma unroll
            for (int p = 0; p < 4; p++) {
                cp16(sA[nxt] + p * rowstep,      Ag + (long)(p * 32) * K + ko);
                cp16(sA[nxt] + p * rowstep + 16, Ag + (long)(p * 32) * K + ko + 4);
                cp16(sB[nxt] + p * rowstep,      Bg + (long)(p * 32) * K + ko);
                cp16(sB[nxt] + p * rowstep + 16, Bg + (long)(p * 32) * K + ko + 4);
            }
            CP_COMMIT();
            CP_WAIT1();
        } else {
            CP_WAIT0();
        }
        __syncthreads();

        const uint32_t aBase = sAbase[cur] + aOff;
        const uint32_t bBase = sBbase[cur] + bOff;

        #pragma unroll
        for (int ks = 0; ks < 4; ks++) {
            const uint32_t kb = (uint32_t)(ks * 8 * 4);
            uint32_t af[4][4], bf[8][2];
            #pragma unroll
            for (int mt = 0; mt < 4; mt++)
                ldm_x4(af[mt], aBase + (uint32_t)(mt * 16 * LDP * 4) + kb);
            #pragma unroll
            for (int np = 0; np < 4; np++) {
                uint32_t d[4];
                ldm_x4(d, bBase + (uint32_t)(np * 16 * LDP * 4) + kb);
                bf[np * 2][0] = d[0]; bf[np * 2][1] = d[1];
                bf[np * 2 + 1][0] = d[2]; bf[np * 2 + 1][1] = d[3];
            }
            #pragma unroll
            for (int mt = 0; mt < 4; mt++)
                #pragma unroll
                for (int nt = 0; nt < 8; nt++)
                    mma_tf32(acc[mt][nt], af[mt], bf[nt]);
        }
        __syncthreads();
    }

    #pragma unroll
    for (int mt = 0; mt < 4; mt++) {
        #pragma unroll
        for (int nt = 0; nt < 8; nt++) {
            const int row = m0 + wm * 64 + mt * 16 + gr;
            const int col = n0 + wn * 64 + nt * 8 + gc * 2;
            float2 lo = make_float2(acc[mt][nt][0], acc[mt][nt][1]);
            float2 hi = make_float2(acc[mt][nt][2], acc[mt][nt][3]);
            if (epi == 1) {
                float2 r0 = *reinterpret_cast<const float2*>(R + (long)row * N + col);
                float2 r1 = *reinterpret_cast<const float2*>(R + (long)(row + 8) * N + col);
                lo.x += r0.x; lo.y += r0.y;
                hi.x += r1.x; hi.y += r1.y;
            } else if (epi == 2) {
                float2 r0 = *reinterpret_cast<const float2*>(R + (long)row * N + col);
                float2 r1 = *reinterpret_cast<const float2*>(R + (long)(row + 8) * N + col);
                lo.x *= r0.x / (1.0f + __expf(-r0.x));
                lo.y *= r0.y / (1.0f + __expf(-r0.y));
                hi.x *= r1.x / (1.0f + __expf(-r1.x));
                hi.y *= r1.y / (1.0f + __expf(-r1.y));
            }
            *reinterpret_cast<float2*>(C + (long)row * N + col) = lo;
            *reinterpret_cast<float2*>(C + (long)(row + 8) * N + col) = hi;
        }
    }
}

// ---------------------------------------------------------------------------
// Tensor-core flash attention (tf32 mma), causal GQA (unchanged from R5)
// ---------------------------------------------------------------------------
#define QS_LD 68
#define KS_LD 68
#define VS_LD 72
#define ATTN_SMEM ((128 * QS_LD + 2 * 64 * KS_LD + 2 * 64 * VS_LD) * 4)

__global__ void __launch_bounds__(128, 2)
attn_mma(const float* __restrict__ q, const float* __restrict__ k,
         const float* __restrict__ v, float* __restrict__ o) {
    extern __shared__ uint32_t smu[];
    uint32_t* Qs = smu;
    uint32_t* Kb[2] = { smu + 128 * QS_LD, smu + 128 * QS_LD + 64 * KS_LD };
    uint32_t* Vb[2] = { Kb[1] + 64 * KS_LD, Kb[1] + 64 * KS_LD + 64 * VS_LD };

    const int tid  = threadIdx.x;
    const int warp = tid >> 5;
    const int lane = tid & 31;
    const int gr = lane >> 2;
    const int gc = lane & 3;
    const int wr = warp << 5;

    const int t0  = blockIdx.x << 7;
    const int bh  = blockIdx.y;
    const int b   = bh >> 4;
    const int hq  = bh & 15;
    const int kvh = hq >> 1;

    const long kvstride = N_KV * HEAD_DIM;
    const int krow = tid >> 1;
    const int kc   = (tid & 1) << 5;
    const float* Kg = k + (long)(b * SEQ + krow) * kvstride + kvh * HEAD_DIM + kc;
    const float* Vg = v + (long)(b * SEQ + krow) * kvstride + kvh * HEAD_DIM + kc;
    uint32_t sK[2], sV[2];
    #pragma unroll
    for (int s = 0; s < 2; s++) {
        sK[s] = cvta_s(&Kb[s][krow * KS_LD + kc]);
        sV[s] = cvta_s(&Vb[s][krow * VS_LD + kc]);
    }

    {
        const int qr = tid >> 2;
        const int qc = (tid & 3) << 4;
        const float* Qg = q + (long)(b * SEQ + t0 + qr) * D_MODEL + hq * HEAD_DIM + qc;
        uint32_t dq = cvta_s(&Qs[qr * QS_LD + qc]);
        #pragma unroll
        for (int p = 0; p < 4; p++) {
            #pragma unroll
            for (int u = 0; u < 4; u++)
                cp16(dq + p * 32 * QS_LD * 4 + u * 16,
                     Qg + (long)(p * 32) * D_MODEL + u * 4);
        }
    }
    {
        #pragma unroll
        for (int u = 0; u < 8; u++) {
            cp16(sK[0] + u * 16, Kg + u * 4);
            cp16(sV[0] + u * 16, Vg + u * 4);
        }
        CP_COMMIT();
    }

    float ofrag[2][8][4];
    #pragma unroll
    for (int mt = 0; mt < 2; mt++)
        #pragma unroll
        for (int nt = 0; nt < 8; nt++)
            #pragma unroll
            for (int r = 0; r < 4; r++) ofrag[mt][nt][r] = 0.f;

    float mrow[2][2] = {{-1e30f, -1e30f}, {-1e30f, -1e30f}};
    float lrow[2][2] = {{0.f, 0.f}, {0.f, 0.f}};
    const float SC = 0.125f;

    const int ntiles = (t0 >> 6) + 2;
    for (int it = 0; it < ntiles; it++) {
        const int s0 = it << 6;
        const int cur = it & 1;

        if (it + 1 < ntiles) {
            const int nxt = cur ^ 1;
            const long off = (long)((it + 1) << 6) * kvstride;
            #pragma unroll
            for (int u = 0; u < 8; u++) {
                cp16(sK[nxt] + u * 16, Kg + off + u * 4);
                cp16(sV[nxt] + u * 16, Vg + off + u * 4);
            }
            CP_COMMIT();
            CP_WAIT1();
        } else {
            CP_WAIT0();
        }
        __syncthreads();

        const uint32_t* Ks = Kb[cur];
        const uint32_t* Vs = Vb[cur];

        float sfrag[2][8][4];
        #pragma unroll
        for (int mt = 0; mt < 2; mt++)
            #pragma unroll
            for (int nt = 0; nt < 8; nt++)
                #pragma unroll
                for (int r = 0; r < 4; r++) sfrag[mt][nt][r] = 0.f;

        #pragma unroll
        for (int ks = 0; ks < 8; ks++) {
            const int k0 = ks * 8 + gc;
            uint32_t aq[2][4];
            #pragma unroll
            for (int mt = 0; mt < 2; mt++) {
                const int r = wr + mt * 16 + gr;
                aq[mt][0] = Qs[r * QS_LD + k0];
                aq[mt][1] = Qs[(r + 8) * QS_LD + k0];
                aq[mt][2] = Qs[r * QS_LD + k0 + 4];
                aq[mt][3] = Qs[(r + 8) * QS_LD + k0 + 4];
            }
            #pragma unroll
            for (int nt = 0; nt < 8; nt++) {
                uint32_t bk[2];
                bk[0] = Ks[(nt * 8 + gr) * KS_LD + k0];
                bk[1] = Ks[(nt * 8 + gr) * KS_LD + k0 + 4];
                mma_tf32(sfrag[0][nt], aq[0], bk);
                mma_tf32(sfrag[1][nt], aq[1], bk);
            }
        }

        if (it >= ntiles - 2) {
            #pragma unroll
            for (int mt = 0; mt < 2; mt++) {
                const int rA = t0 + wr + mt * 16 + gr;
                const int rB = rA + 8;
                #pragma unroll
                for (int nt = 0; nt < 8; nt++) {
                    const int cb = s0 + nt * 8 + 2 * gc;
                    if (cb     > rA) sfrag[mt][nt][0] = -1e30f;
                    if (cb + 1 > rA) sfrag[mt][nt][1] = -1e30f;
                    if (cb     > rB) sfrag[mt][nt][2] = -1e30f;
                    if (cb + 1 > rB) sfrag[mt][nt][3] = -1e30f;
                }
            }
        }

        #pragma unroll
        for (int mt = 0; mt < 2; mt++) {
            float r0 = -1e30f, r1 = -1e30f;
            #pragma unroll
            for (int nt = 0; nt < 8; nt++) {
                r0 = fmaxf(r0, fmaxf(sfrag[mt][nt][0], sfrag[mt][nt][1]));
                r1 = fmaxf(r1, fmaxf(sfrag[mt][nt][2], sfrag[mt][nt][3]));
            }
            r0 = fmaxf(r0, __shfl_xor_sync(0xffffffffu, r0, 1));
            r0 = fmaxf(r0, __shfl_xor_sync(0xffffffffu, r0, 2));
            r1 = fmaxf(r1, __shfl_xor_sync(0xffffffffu, r1, 1));
            r1 = fmaxf(r1, __shfl_xor_sync(0xffffffffu, r1, 2));

            const float mn0 = fmaxf(mrow[mt][0], r0);
            const float mn1 = fmaxf(mrow[mt][1], r1);
            const float c0 = __expf((mrow[mt][0] - mn0) * SC);
            const float c1 = __expf((mrow[mt][1] - mn1) * SC);
            lrow[mt][0] *= c0;
            lrow[mt][1] *= c1;
            #pragma unroll
            for (int nt = 0; nt < 8; nt++) {
                ofrag[mt][nt][0] *= c0; ofrag[mt][nt][1] *= c0;
                ofrag[mt][nt][2] *= c1; ofrag[mt][nt][3] *= c1;
            }
            float s0s = 0.f, s1s = 0.f;
            #pragma unroll
            for (int nt = 0; nt < 8; nt++) {
                sfrag[mt][nt][0] = __expf((sfrag[mt][nt][0] - mn0) * SC);
                sfrag[mt][nt][1] = __expf((sfrag[mt][nt][1] - mn0) * SC);
                sfrag[mt][nt][2] = __expf((sfrag[mt][nt][2] - mn1) * SC);
                sfrag[mt][nt][3] = __expf((sfrag[mt][nt][3] - mn1) * SC);
                s0s += sfrag[mt][nt][0] + sfrag[mt][nt][1];
                s1s += sfrag[mt][nt][2] + sfrag[mt][nt][3];
            }
            s0s += __shfl_xor_sync(0xffffffffu, s0s, 1);
            s0s += __shfl_xor_sync(0xffffffffu, s0s, 2);
            s1s += __shfl_xor_sync(0xffffffffu, s1s, 1);
            s1s += __shfl_xor_sync(0xffffffffu, s1s, 2);
            lrow[mt][0] += s0s;
            lrow[mt][1] += s1s;
            mrow[mt][0] = mn0;
            mrow[mt][1] = mn1;
        }

        const int srcA = (gr << 2) | (gc >> 1);
        const bool odd = gc & 1;
        #pragma unroll
        for (int ks = 0; ks < 8; ks++) {
            uint32_t ap[2][4];
            #pragma unroll
            for (int mt = 0; mt < 2; mt++) {
                const float p0 = sfrag[mt][ks][0], p1 = sfrag[mt][ks][1];
                const float p2 = sfrag[mt][ks][2], p3 = sfrag[mt][ks][3];
                const float v00 = __shfl_sync(0xffffffffu, p0, srcA);
                const float v01 = __shfl_sync(0xffffffffu, p1, srcA);
                const float v10 = __shfl_sync(0xffffffffu, p0, srcA + 2);
                const float v11 = __shfl_sync(0xffffffffu, p1, srcA + 2);
                const float w00 = __shfl_sync(0xffffffffu, p2, srcA);
                const float w01 = __shfl_sync(0xffffffffu, p3, srcA);
                const float w10 = __shfl_sync(0xffffffffu, p2, srcA + 2);
                const float w11 = __shfl_sync(0xffffffffu, p3, srcA + 2);
                ap[mt][0] = __float_as_uint(odd ? v01 : v00);
                ap[mt][1] = __float_as_uint(odd ? w01 : w00);
                ap[mt][2] = __float_as_uint(odd ? v11 : v10);
                ap[mt][3] = __float_as_uint(odd ? w11 : w10);
            }
            #pragma unroll
            for (int nt = 0; nt < 8; nt++) {
                uint32_t bv2[2];
                bv2[0] = Vs[(ks * 8 + gc) * VS_LD + nt * 8 + gr];
                bv2[1] = Vs[(ks * 8 + gc + 4) * VS_LD + nt * 8 + gr];
                mma_tf32(ofrag[0][nt], ap[0], bv2);
                mma_tf32(ofrag[1][nt], ap[1], bv2);
            }
        }
        __syncthreads();
    }

    #pragma unroll
    for (int mt = 0; mt < 2; mt++) {
        const int rowA = t0 + wr + mt * 16 + gr;
        const int rowB = rowA + 8;
        const float il0 = 1.0f / lrow[mt][0];
        const float il1 = 1.0f / lrow[mt][1];
        #pragma unroll
        for (int nt = 0; nt < 8; nt++) {
            const int col = hq * HEAD_DIM + nt * 8 + 2 * gc;
            float2 lo = make_float2(ofrag[mt][nt][0] * il0, ofrag[mt][nt][1] * il0);
            float2 hi = make_float2(ofrag[mt][nt][2] * il1, ofrag[mt][nt][3] * il1);
            *reinterpret_cast<float2*>(o + (long)(b * SEQ + rowA) * D_MODEL + col) = lo;
            *reinterpret_cast<float2*>(o + (long)(b * SEQ + rowB) * D_MODEL + col) = hi;
        }
    }
}

// ---------------------------------------------------------------------------
// Transpose + tf32-round (RNA) weights: in [R,C] -> out [C,R]
// ---------------------------------------------------------------------------
__global__ void transpose_kernel(const float* __restrict__ in,
                                 float* __restrict__ out, int R, int C) {
    __shared__ float t[32][33];
    const int c0 = blockIdx.x << 5, r0 = blockIdx.y << 5;
    #pragma unroll
    for (int dy = 0; dy < 32; dy += 8) {
        float vv = in[(long)(r0 + threadIdx.y + dy) * C + c0 + threadIdx.x];
        t[threadIdx.y + dy][threadIdx.x] = __uint_as_float(f2tf32(vv));
    }
    __syncthreads();
    #pragma unroll
    for (int dy = 0; dy < 32; dy += 8) {
        out[(long)(c0 + threadIdx.y + dy) * R + r0 + threadIdx.x] =
            t[threadIdx.x][threadIdx.y + dy];
    }
}

// ---------------------------------------------------------------------------
// RMSNorm
// ---------------------------------------------------------------------------
__global__ void rmsnorm_kernel(const float* __restrict__ x,
                               const float* __restrict__ g,
                               float* __restrict__ out) {
    const int row = blockIdx.x;
    const int tid = threadIdx.x;
    const float* xr = x + (long)row * D_MODEL;
    float4 v = *reinterpret_cast<const float4*>(xr + tid * 4);
    float s = v.x * v.x + v.y * v.y + v.z * v.z + v.w * v.w;

    #pragma unroll
    for (int off = 16; off > 0; off >>= 1)
        s += __shfl_xor_sync(0xffffffffu, s, off);

    __shared__ float red[8];
    if ((tid & 31) == 0) red[tid >> 5] = s;
    __syncthreads();
    float total;
    {
        float t = (tid < 8) ? red[tid] : 0.f;
        #pragma unroll
        for (int off = 4; off > 0; off >>= 1)
            t += __shfl_xor_sync(0xffffffffu, t, off);
        __shared__ float bc;
        if (tid == 0) bc = t;
        __syncthreads();
        total = bc;
    }
    float inv = rsqrtf(total * (1.0f / D_MODEL) + 1e-6f);
    float4 gv = *reinterpret_cast<const float4*>(g + tid * 4);
    float4 o;
    o.x = v.x * inv * gv.x;
    o.y = v.y * inv * gv.y;
    o.z = v.z * inv * gv.z;
    o.w = v.w * inv * gv.w;
    *reinterpret_cast<float4*>(out + (long)row * D_MODEL + tid * 4) = o;
}

// ---------------------------------------------------------------------------
// RoPE (half-split, in place)
// ---------------------------------------------------------------------------
__global__ void rope_kernel(float* __restrict__ q, float* __restrict__ k) {
    const int row = blockIdx.x;
    const int t = row & (SEQ - 1);
    const int tid = threadIdx.x;

    float* ptr;
    int j;
    if (tid < 512) {
        int h = tid >> 5; j = tid & 31;
        ptr = q + (long)row * D_MODEL + h * HEAD_DIM;
    } else {
        int u = tid - 512;
        int h = u >> 5; j = u & 31;
        ptr = k + (long)row * (N_KV * HEAD_DIM) + h * HEAD_DIM;
    }
    float inv = (float)exp(-(double)j / 32.0 * 9.210340371976184);
    float fr = (float)t * inv;
    float c = cosf(fr), s = sinf(fr);
    float x1 = ptr[j], x2 = ptr[j + 32];
    ptr[j]      = x1 * c - x2 * s;
    ptr[j + 32] = x2 * c + x1 * s;
}

// ---------------------------------------------------------------------------
// Launch
// ---------------------------------------------------------------------------
extern "C" void kernel_launch(void* const* d_in, const int* in_sizes, int n_in,
                              void* d_out, int out_size) {
    const float* x  = (const float*)d_in[0];
    const float* g1 = (const float*)d_in[1];
    const float* g2 = (const float*)d_in[2];
    const float* wq = (const float*)d_in[3];
    const float* wk = (const float*)d_in[4];
    const float* wv = (const float*)d_in[5];
    const float* wo = (const float*)d_in[6];
    const float* w1 = (const float*)d_in[7];
    const float* w2 = (const float*)d_in[8];
    const float* w3 = (const float*)d_in[9];
    float* out = (float*)d_out;

    float *h, *q, *k, *v, *ao, *h2, *a, *bb;
    float *wqT, *wkT, *wvT, *woT, *w1T, *w2T, *w3T;
    cudaGetSymbolAddress((void**)&h,  g_h);
    cudaGetSymbolAddress((void**)&q,  g_q);
    cudaGetSymbolAddress((void**)&k,  g_k);
    cudaGetSymbolAddress((void**)&v,  g_v);
    cudaGetSymbolAddress((void**)&ao, g_ao);
    cudaGetSymbolAddress((void**)&h2, g_h2);
    cudaGetSymbolAddress((void**)&a,  g_a);
    cudaGetSymbolAddress((void**)&bb, g_b);
    cudaGetSymbolAddress((void**)&wqT, g_wqT);
    cudaGetSymbolAddress((void**)&wkT, g_wkT);
    cudaGetSymbolAddress((void**)&wvT, g_wvT);
    cudaGetSymbolAddress((void**)&woT, g_woT);
    cudaGetSymbolAddress((void**)&w1T, g_w1T);
    cudaGetSymbolAddress((void**)&w2T, g_w2T);
    cudaGetSymbolAddress((void**)&w3T, g_w3T);

    cudaFuncSetAttribute(tc_gemm, cudaFuncAttributeMaxDynamicSharedMemorySize,
                         GEMM_SMEM_BYTES);
    cudaFuncSetAttribute(attn_mma, cudaFuncAttributeMaxDynamicSharedMemorySize,
                         ATTN_SMEM);

    dim3 tb(32, 8);
    transpose_kernel<<<dim3(D_MODEL / 32, D_MODEL / 32), tb>>>(wq, wqT, D_MODEL, D_MODEL);
    transpose_kernel<<<dim3((N_KV * HEAD_DIM) / 32, D_MODEL / 32), tb>>>(wk, wkT, D_MODEL, N_KV * HEAD_DIM);
    transpose_kernel<<<dim3((N_KV * HEAD_DIM) / 32, D_MODEL / 32), tb>>>(wv, wvT, D_MODEL, N_KV * HEAD_DIM);
    transpose_kernel<<<dim3(D_MODEL / 32, D_MODEL / 32), tb>>>(wo, woT, D_MODEL, D_MODEL);
    transpose_kernel<<<dim3(HIDDEN / 32, D_MODEL / 32), tb>>>(w1, w1T, D_MODEL, HIDDEN);
    transpose_kernel<<<dim3(HIDDEN / 32, D_MODEL / 32), tb>>>(w2, w2T, D_MODEL, HIDDEN);
    transpose_kernel<<<dim3(D_MODEL / 32, HIDDEN / 32), tb>>>(w3, w3T, HIDDEN, D_MODEL);

    rmsnorm_kernel<<<BT, 256>>>(x, g1, h);

    tc_gemm<<<dim3(D_MODEL / 128, BT / 128), 128, GEMM_SMEM_BYTES>>>(h, wqT, nullptr, q, BT, D_MODEL, D_MODEL, 0);
    tc_gemm<<<dim3((N_KV * HEAD_DIM) / 128, BT / 128), 128, GEMM_SMEM_BYTES>>>(h, wkT, nullptr, k, BT, N_KV * HEAD_DIM, D_MODEL, 0);
    tc_gemm<<<dim3((N_KV * HEAD_DIM) / 128, BT / 128), 128, GEMM_SMEM_BYTES>>>(h, wvT, nullptr, v, BT, N_KV * HEAD_DIM, D_MODEL, 0);

    rope_kernel<<<BT, 768>>>(q, k);

    attn_mma<<<dim3(SEQ / 128, BATCH * N_HEADS), 128, ATTN_SMEM>>>(q, k, v, ao);

    tc_gemm<<<dim3(D_MODEL / 128, BT / 128), 128, GEMM_SMEM_BYTES>>>(ao, woT, x, out, BT, D_MODEL, D_MODEL, 1);

    rmsnorm_kernel<<<BT, 256>>>(out, g2, h2);

    tc_gemm<<<dim3(HIDDEN / 128, BT / 128), 128, GEMM_SMEM_BYTES>>>(h2, w1T, nullptr, a,  BT, HIDDEN, D_MODEL, 0);
    // b = h2 @ w2 with fused epilogue: a <- silu(a) * b
    tc_gemm<<<dim3(HIDDEN / 128, BT / 128), 128, GEMM_SMEM_BYTES>>>(h2, w2T, a, a, BT, HIDDEN, D_MODEL, 2);

    tc_gemm<<<dim3(D_MODEL / 128, BT / 128), 128, GEMM_SMEM_BYTES>>>(a, w3T, out, out, BT, D_MODEL, HIDDEN, 1);
}

// round 8
// speedup vs baseline: 1.7997x; 1.7997x over previous
#include <cuda_runtime.h>
#include <cuda_fp16.h>
#include <math.h>
#include <stdint.h>

// ---------------------------------------------------------------------------
// Problem constants
// ---------------------------------------------------------------------------
#define D_MODEL   1024
#define N_HEADS   16
#define N_KV      8
#define HEAD_DIM  64
#define HIDDEN    4096
#define BATCH     4
#define SEQ       2048
#define BT        (BATCH * SEQ)
#define QKV_N     2048                   // 1024 q + 512 k + 512 v

// ---------------------------------------------------------------------------
// Scratch (device globals)
// ---------------------------------------------------------------------------
__device__ __half g_h  [BT * D_MODEL];          // rmsnorm1 out (half)
__device__ float  g_qkv[BT * QKV_N];            // fused qkv (fp32, for attn)
__device__ __half g_ao [BT * D_MODEL];          // attention out (half)
__device__ __half g_h2 [BT * D_MODEL];          // rmsnorm2 out (half)
__device__ __half g_a  [BT * HIDDEN];           // w1 branch (half)
__device__ __half g_a2 [BT * HIDDEN];           // silu(a)*b (half)

__device__ __half g_wqkvT[QKV_N * D_MODEL];     // [2048,1024] K-contiguous
__device__ __half g_woT[D_MODEL * D_MODEL];
__device__ __half g_w1T[HIDDEN * D_MODEL];
__device__ __half g_w2T[HIDDEN * D_MODEL];
__device__ __half g_w3T[D_MODEL * HIDDEN];

// ---------------------------------------------------------------------------
// Helpers
// ---------------------------------------------------------------------------
__device__ __forceinline__ void mma_f16(float* c, const uint32_t* a, const uint32_t* b) {
    asm volatile(
        "mma.sync.aligned.m16n8k16.row.col.f32.f16.f16.f32 "
        "{%0,%1,%2,%3}, {%4,%5,%6,%7}, {%8,%9}, {%0,%1,%2,%3};\n"
        : "+f"(c[0]), "+f"(c[1]), "+f"(c[2]), "+f"(c[3])
        : "r"(a[0]), "r"(a[1]), "r"(a[2]), "r"(a[3]), "r"(b[0]), "r"(b[1]));
}
__device__ __forceinline__ void mma_tf32(float* c, const uint32_t* a, const uint32_t* b) {
    asm volatile(
        "mma.sync.aligned.m16n8k8.row.col.f32.tf32.tf32.f32 "
        "{%0,%1,%2,%3}, {%4,%5,%6,%7}, {%8,%9}, {%0,%1,%2,%3};\n"
        : "+f"(c[0]), "+f"(c[1]), "+f"(c[2]), "+f"(c[3])
        : "r"(a[0]), "r"(a[1]), "r"(a[2]), "r"(a[3]), "r"(b[0]), "r"(b[1]));
}
__device__ __forceinline__ void ldm_x4(uint32_t* d, uint32_t saddr) {
    asm volatile(
        "ldmatrix.sync.aligned.m8n8.x4.shared.b16 {%0,%1,%2,%3}, [%4];"
        : "=r"(d[0]), "=r"(d[1]), "=r"(d[2]), "=r"(d[3]) : "r"(saddr));
}
__device__ __forceinline__ uint32_t cvta_s(const void* p) {
    return (uint32_t)__cvta_generic_to_shared(p);
}
__device__ __forceinline__ void cp16(uint32_t dst, const void* src) {
    asm volatile(
        "{ .reg .u64 g; cvta.to.global.u64 g, %1; "
        "cp.async.cg.shared.global [%0], [g], 16; }"
        :: "r"(dst), "l"(src) : "memory");
}
#define CP_COMMIT() asm volatile("cp.async.commit_group;\n" ::: "memory")
#define CP_WAIT1()  asm volatile("cp.async.wait_group 1;\n" ::: "memory")
#define CP_WAIT0()  asm volatile("cp.async.wait_group 0;\n" ::: "memory")

__device__ __forceinline__ uint32_t h2_u32(__half2 h) {
    uint32_t u;
    *reinterpret_cast<__half2*>(&u) = h;
    return u;
}

// epilogue modes
#define EPI_F32   0   // C fp32 = acc
#define EPI_RES   1   // C fp32 = acc + R(fp32)
#define EPI_HALF  2   // C half = acc
#define EPI_SILU  3   // C half = silu(R half) * acc

// ---------------------------------------------------------------------------
// fp16 tensor-core GEMM: C[M,N] = A[M,K] @ Bt[N,K]^T
// CTA 128 threads, 2x2 warps, warp tile 64x64, BK=32 halves,
// 3-stage cp.async ring (one __syncthreads per chunk), ldmatrix.x4.
// ---------------------------------------------------------------------------
#define BKH   32                         // K-chunk in halves
#define LDH   40                         // row stride in halves (80 B)
#define STG_H (128 * LDH)                // halves per operand stage
#define GEMM_SMEM_BYTES (6 * STG_H * 2)  // 3 stages x (A+B) = 61440 B

__global__ void __launch_bounds__(128, 2)
hgemm(const __half* __restrict__ A, const __half* __restrict__ Bt,
      const void* __restrict__ Rv, void* __restrict__ Cv,
      int M, int N, int K, int epi) {
    extern __shared__ __half smh[];
    __half* Abuf[3] = { smh, smh + 2 * STG_H, smh + 4 * STG_H };
    __half* Bbuf[3] = { smh + STG_H, smh + 3 * STG_H, smh + 5 * STG_H };

    const int tid  = threadIdx.x;
    const int wid  = tid >> 5;
    const int lane = tid & 31;
    const int wm   = wid >> 1;
    const int wn   = wid & 1;
    const int gr   = lane >> 2;
    const int gc   = lane & 3;
    const int m0 = blockIdx.y << 7;
    const int n0 = blockIdx.x << 7;

    const int lr = tid >> 2;
    const int lc = (tid & 3) << 3;
    const __half* Ag = A  + (long)(m0 + lr) * K + lc;
    const __half* Bg = Bt + (long)(n0 + lr) * K + lc;

    uint32_t sA[3], sB[3], sAb[3], sBb[3];
    #pragma unroll
    for (int s = 0; s < 3; s++) {
        sAb[s] = cvta_s(Abuf[s]);
        sBb[s] = cvta_s(Bbuf[s]);
        sA[s] = cvta_s(&Abuf[s][lr * LDH + lc]);
        sB[s] = cvta_s(&Bbuf[s][lr * LDH + lc]);
    }
    const uint32_t rowstep = 32 * LDH * 2;   // 32 rows, bytes

    // ldmatrix per-lane base offsets (bytes)
    const int l7  = lane & 7;
    const int sel = lane >> 3;               // 0..3
    const uint32_t aOff = (uint32_t)(((wm * 64 + l7 + (sel & 1) * 8) * LDH + (sel >> 1) * 8) * 2);
    const uint32_t bOff = (uint32_t)(((wn * 64 + l7 + (sel >> 1) * 8) * LDH + (sel & 1) * 8) * 2);

    const int NC = K / BKH;

    float acc[4][8][4];
    #pragma unroll
    for (int i = 0; i < 4; i++)
        #pragma unroll
        for (int j = 0; j < 8; j++)
            #pragma unroll
            for (int q = 0; q < 4; q++) acc[i][j][q] = 0.f;

    // prologue: issue chunks 0 and 1
    #pragma unroll
    for (int c0i = 0; c0i < 2; c0i++) {
        const long ko = (long)c0i * BKH;
        #pragma unroll
        for (int p = 0; p < 4; p++) {
            cp16(sA[c0i] + p * rowstep, Ag + (long)(p * 32) * K + ko);
            cp16(sB[c0i] + p * rowstep, Bg + (long)(p * 32) * K + ko);
        }
        CP_COMMIT();
    }

    for (int i = 0; i < NC; i++) {
        if (i < NC - 1) CP_WAIT1(); else CP_WAIT0();
        __syncthreads();

        if (i + 2 < NC) {
            const int s2 = (i + 2) % 3;
            const long ko = (long)(i + 2) * BKH;
            #pragma unroll
            for (int p = 0; p < 4; p++) {
                cp16(sA[s2] + p * rowstep, Ag + (long)(p * 32) * K + ko);
                cp16(sB[s2] + p * rowstep, Bg + (long)(p * 32) * K + ko);
            }
            CP_COMMIT();
        }

        const int cur = i % 3;
        const uint32_t aBase = sAb[cur] + aOff;
        const uint32_t bBase = sBb[cur] + bOff;

        #pragma unroll
        for (int ks = 0; ks < 2; ks++) {          // 2 k-steps of 16 halves
            const uint32_t kb = (uint32_t)(ks * 16 * 2);
            uint32_t af[4][4], bf[8][2];
            #pragma unroll
            for (int mt = 0; mt < 4; mt++)
                ldm_x4(af[mt], aBase + (uint32_t)(mt * 16 * LDH * 2) + kb);
            #pragma unroll
            for (int np = 0; np < 4; np++) {
                uint32_t d[4];
                ldm_x4(d, bBase + (uint32_t)(np * 16 * LDH * 2) + kb);
                bf[np * 2][0]     = d[0]; bf[np * 2][1]     = d[1];
                bf[np * 2 + 1][0] = d[2]; bf[np * 2 + 1][1] = d[3];
            }
            #pragma unroll
            for (int mt = 0; mt < 4; mt++)
                #pragma unroll
                for (int nt = 0; nt < 8; nt++)
                    mma_f16(acc[mt][nt], af[mt], bf[nt]);
        }
    }
    __syncthreads();

    // epilogue
    #pragma unroll
    for (int mt = 0; mt < 4; mt++) {
        #pragma unroll
        for (int nt = 0; nt < 8; nt++) {
            const int row = m0 + wm * 64 + mt * 16 + gr;
            const int col = n0 + wn * 64 + nt * 8 + gc * 2;
            const long offA = (long)row * N + col;
            const long offB = (long)(row + 8) * N + col;
            float2 lo = make_float2(acc[mt][nt][0], acc[mt][nt][1]);
            float2 hi = make_float2(acc[mt][nt][2], acc[mt][nt][3]);
            if (epi == EPI_F32) {
                *reinterpret_cast<float2*>((float*)Cv + offA) = lo;
                *reinterpret_cast<float2*>((float*)Cv + offB) = hi;
            } else if (epi == EPI_RES) {
                const float* R = (const float*)Rv;
                float2 r0 = *reinterpret_cast<const float2*>(R + offA);
                float2 r1 = *reinterpret_cast<const float2*>(R + offB);
                lo.x += r0.x; lo.y += r0.y;
                hi.x += r1.x; hi.y += r1.y;
                *reinterpret_cast<float2*>((float*)Cv + offA) = lo;
                *reinterpret_cast<float2*>((float*)Cv + offB) = hi;
            } else if (epi == EPI_HALF) {
                *reinterpret_cast<__half2*>((__half*)Cv + offA) = __floats2half2_rn(lo.x, lo.y);
                *reinterpret_cast<__half2*>((__half*)Cv + offB) = __floats2half2_rn(hi.x, hi.y);
            } else {  // EPI_SILU
                const __half* R = (const __half*)Rv;
                float2 r0 = __half22float2(*reinterpret_cast<const __half2*>(R + offA));
                float2 r1 = __half22float2(*reinterpret_cast<const __half2*>(R + offB));
                lo.x *= r0.x / (1.0f + __expf(-r0.x));
                lo.y *= r0.y / (1.0f + __expf(-r0.y));
                hi.x *= r1.x / (1.0f + __expf(-r1.x));
                hi.y *= r1.y / (1.0f + __expf(-r1.y));
                *reinterpret_cast<__half2*>((__half*)Cv + offA) = __floats2half2_rn(lo.x, lo.y);
                *reinterpret_cast<__half2*>((__half*)Cv + offB) = __floats2half2_rn(hi.x, hi.y);
            }
        }
    }
}

// ---------------------------------------------------------------------------
// Tensor-core flash attention (tf32 mma), causal GQA.
// Reads fused qkv fp32 (row stride 2048); writes ao as half.
// ---------------------------------------------------------------------------
#define QS_LD 68
#define KS_LD 68
#define VS_LD 72
#define ATTN_SMEM ((128 * QS_LD + 2 * 64 * KS_LD + 2 * 64 * VS_LD) * 4)

__global__ void __launch_bounds__(128, 2)
attn_mma(const float* __restrict__ qkv, __half* __restrict__ o) {
    extern __shared__ uint32_t smu[];
    uint32_t* Qs = smu;
    uint32_t* Kb[2] = { smu + 128 * QS_LD, smu + 128 * QS_LD + 64 * KS_LD };
    uint32_t* Vb[2] = { Kb[1] + 64 * KS_LD, Kb[1] + 64 * KS_LD + 64 * VS_LD };

    const int tid  = threadIdx.x;
    const int warp = tid >> 5;
    const int lane = tid & 31;
    const int gr = lane >> 2;
    const int gc = lane & 3;
    const int wr = warp << 5;

    const int t0  = blockIdx.x << 7;
    const int bh  = blockIdx.y;
    const int b   = bh >> 4;
    const int hq  = bh & 15;
    const int kvh = hq >> 1;

    const int krow = tid >> 1;
    const int kc   = (tid & 1) << 5;
    const float* Kg = qkv + (long)(b * SEQ + krow) * QKV_N + 1024 + kvh * HEAD_DIM + kc;
    const float* Vg = qkv + (long)(b * SEQ + krow) * QKV_N + 1536 + kvh * HEAD_DIM + kc;
    uint32_t sK[2], sV[2];
    #pragma unroll
    for (int s = 0; s < 2; s++) {
        sK[s] = cvta_s(&Kb[s][krow * KS_LD + kc]);
        sV[s] = cvta_s(&Vb[s][krow * VS_LD + kc]);
    }

    {
        const int qr = tid >> 2;
        const int qc = (tid & 3) << 4;
        const float* Qg = qkv + (long)(b * SEQ + t0 + qr) * QKV_N + hq * HEAD_DIM + qc;
        uint32_t dq = cvta_s(&Qs[qr * QS_LD + qc]);
        #pragma unroll
        for (int p = 0; p < 4; p++) {
            #pragma unroll
            for (int u = 0; u < 4; u++)
                cp16(dq + p * 32 * QS_LD * 4 + u * 16,
                     Qg + (long)(p * 32) * QKV_N + u * 4);
        }
    }
    {
        #pragma unroll
        for (int u = 0; u < 8; u++) {
            cp16(sK[0] + u * 16, Kg + u * 4);
            cp16(sV[0] + u * 16, Vg + u * 4);
        }
        CP_COMMIT();
    }

    float ofrag[2][8][4];
    #pragma unroll
    for (int mt = 0; mt < 2; mt++)
        #pragma unroll
        for (int nt = 0; nt < 8; nt++)
            #pragma unroll
            for (int r = 0; r < 4; r++) ofrag[mt][nt][r] = 0.f;

    float mrow[2][2] = {{-1e30f, -1e30f}, {-1e30f, -1e30f}};
    float lrow[2][2] = {{0.f, 0.f}, {0.f, 0.f}};
    const float SC = 0.125f;

    const int ntiles = (t0 >> 6) + 2;
    for (int it = 0; it < ntiles; it++) {
        const int s0 = it << 6;
        const int cur = it & 1;

        if (it + 1 < ntiles) {
            const int nxt = cur ^ 1;
            const long off = (long)((it + 1) << 6) * QKV_N;
            #pragma unroll
            for (int u = 0; u < 8; u++) {
                cp16(sK[nxt] + u * 16, Kg + off + u * 4);
                cp16(sV[nxt] + u * 16, Vg + off + u * 4);
            }
            CP_COMMIT();
            CP_WAIT1();
        } else {
            CP_WAIT0();
        }
        __syncthreads();

        const uint32_t* Ks = Kb[cur];
        const uint32_t* Vs = Vb[cur];

        float sfrag[2][8][4];
        #pragma unroll
        for (int mt = 0; mt < 2; mt++)
            #pragma unroll
            for (int nt = 0; nt < 8; nt++)
                #pragma unroll
                for (int r = 0; r < 4; r++) sfrag[mt][nt][r] = 0.f;

        #pragma unroll
        for (int ks = 0; ks < 8; ks++) {
            const int k0 = ks * 8 + gc;
            uint32_t aq[2][4];
            #pragma unroll
            for (int mt = 0; mt < 2; mt++) {
                const int r = wr + mt * 16 + gr;
                aq[mt][0] = Qs[r * QS_LD + k0];
                aq[mt][1] = Qs[(r + 8) * QS_LD + k0];
                aq[mt][2] = Qs[r * QS_LD + k0 + 4];
                aq[mt][3] = Qs[(r + 8) * QS_LD + k0 + 4];
            }
            #pragma unroll
            for (int nt = 0; nt < 8; nt++) {
                uint32_t bk[2];
                bk[0] = Ks[(nt * 8 + gr) * KS_LD + k0];
                bk[1] = Ks[(nt * 8 + gr) * KS_LD + k0 + 4];
                mma_tf32(sfrag[0][nt], aq[0], bk);
                mma_tf32(sfrag[1][nt], aq[1], bk);
            }
        }

        if (it >= ntiles - 2) {
            #pragma unroll
            for (int mt = 0; mt < 2; mt++) {
                const int rA = t0 + wr + mt * 16 + gr;
                const int rB = rA + 8;
                #pragma unroll
                for (int nt = 0; nt < 8; nt++) {
                    const int cb = s0 + nt * 8 + 2 * gc;
                    if (cb     > rA) sfrag[mt][nt][0] = -1e30f;
                    if (cb + 1 > rA) sfrag[mt][nt][1] = -1e30f;
                    if (cb     > rB) sfrag[mt][nt][2] = -1e30f;
                    if (cb + 1 > rB) sfrag[mt][nt][3] = -1e30f;
                }
            }
        }

        #pragma unroll
        for (int mt = 0; mt < 2; mt++) {
            float r0 = -1e30f, r1 = -1e30f;
            #pragma unroll
            for (int nt = 0; nt < 8; nt++) {
                r0 = fmaxf(r0, fmaxf(sfrag[mt][nt][0], sfrag[mt][nt][1]));
                r1 = fmaxf(r1, fmaxf(sfrag[mt][nt][2], sfrag[mt][nt][3]));
            }
            r0 = fmaxf(r0, __shfl_xor_sync(0xffffffffu, r0, 1));
            r0 = fmaxf(r0, __shfl_xor_sync(0xffffffffu, r0, 2));
            r1 = fmaxf(r1, __shfl_xor_sync(0xffffffffu, r1, 1));
            r1 = fmaxf(r1, __shfl_xor_sync(0xffffffffu, r1, 2));

            const float mn0 = fmaxf(mrow[mt][0], r0);
            const float mn1 = fmaxf(mrow[mt][1], r1);
            const float c0 = __expf((mrow[mt][0] - mn0) * SC);
            const float c1 = __expf((mrow[mt][1] - mn1) * SC);
            lrow[mt][0] *= c0;
            lrow[mt][1] *= c1;
            #pragma unroll
            for (int nt = 0; nt < 8; nt++) {
                ofrag[mt][nt][0] *= c0; ofrag[mt][nt][1] *= c0;
                ofrag[mt][nt][2] *= c1; ofrag[mt][nt][3] *= c1;
            }
            float s0s = 0.f, s1s = 0.f;
            #pragma unroll
            for (int nt = 0; nt < 8; nt++) {
                sfrag[mt][nt][0] = __expf((sfrag[mt][nt][0] - mn0) * SC);
                sfrag[mt][nt][1] = __expf((sfrag[mt][nt][1] - mn0) * SC);
                sfrag[mt][nt][2] = __expf((sfrag[mt][nt][2] - mn1) * SC);
                sfrag[mt][nt][3] = __expf((sfrag[mt][nt][3] - mn1) * SC);
                s0s += sfrag[mt][nt][0] + sfrag[mt][nt][1];
                s1s += sfrag[mt][nt][2] + sfrag[mt][nt][3];
            }
            s0s += __shfl_xor_sync(0xffffffffu, s0s, 1);
            s0s += __shfl_xor_sync(0xffffffffu, s0s, 2);
            s1s += __shfl_xor_sync(0xffffffffu, s1s, 1);
            s1s += __shfl_xor_sync(0xffffffffu, s1s, 2);
            lrow[mt][0] += s0s;
            lrow[mt][1] += s1s;
            mrow[mt][0] = mn0;
            mrow[mt][1] = mn1;
        }

        const int srcA = (gr << 2) | (gc >> 1);
        const bool odd = gc & 1;
        #pragma unroll
        for (int ks = 0; ks < 8; ks++) {
            uint32_t ap[2][4];
            #pragma unroll
            for (int mt = 0; mt < 2; mt++) {
                const float p0 = sfrag[mt][ks][0], p1 = sfrag[mt][ks][1];
                const float p2 = sfrag[mt][ks][2], p3 = sfrag[mt][ks][3];
                const float v00 = __shfl_sync(0xffffffffu, p0, srcA);
                const float v01 = __shfl_sync(0xffffffffu, p1, srcA);
                const float v10 = __shfl_sync(0xffffffffu, p0, srcA + 2);
                const float v11 = __shfl_sync(0xffffffffu, p1, srcA + 2);
                const float w00 = __shfl_sync(0xffffffffu, p2, srcA);
                const float w01 = __shfl_sync(0xffffffffu, p3, srcA);
                const float w10 = __shfl_sync(0xffffffffu, p2, srcA + 2);
                const float w11 = __shfl_sync(0xffffffffu, p3, srcA + 2);
                ap[mt][0] = __float_as_uint(odd ? v01 : v00);
                ap[mt][1] = __float_as_uint(odd ? w01 : w00);
                ap[mt][2] = __float_as_uint(odd ? v11 : v10);
                ap[mt][3] = __float_as_uint(odd ? w11 : w10);
            }
            #pragma unroll
            for (int nt = 0; nt < 8; nt++) {
                uint32_t bv2[2];
                bv2[0] = Vs[(ks * 8 + gc) * VS_LD + nt * 8 + gr];
                bv2[1] = Vs[(ks * 8 + gc + 4) * VS_LD + nt * 8 + gr];
                mma_tf32(ofrag[0][nt], ap[0], bv2);
                mma_tf32(ofrag[1][nt], ap[1], bv2);
            }
        }
        __syncthreads();
    }

    #pragma unroll
    for (int mt = 0; mt < 2; mt++) {
        const int rowA = t0 + wr + mt * 16 + gr;
        const int rowB = rowA + 8;
        const float il0 = 1.0f / lrow[mt][0];
        const float il1 = 1.0f / lrow[mt][1];
        #pragma unroll
        for (int nt = 0; nt < 8; nt++) {
            const int col = hq * HEAD_DIM + nt * 8 + 2 * gc;
            *reinterpret_cast<__half2*>(o + (long)(b * SEQ + rowA) * D_MODEL + col) =
                __floats2half2_rn(ofrag[mt][nt][0] * il0, ofrag[mt][nt][1] * il0);
            *reinterpret_cast<__half2*>(o + (long)(b * SEQ + rowB) * D_MODEL + col) =
                __floats2half2_rn(ofrag[mt][nt][2] * il1, ofrag[mt][nt][3] * il1);
        }
    }
}

// ---------------------------------------------------------------------------
// Transpose to half: in [R,C] fp32 -> out [C,R] half
// ---------------------------------------------------------------------------
__global__ void transpose_h(const float* __restrict__ in,
                            __half* __restrict__ out, int R, int C) {
    __shared__ float t[32][33];
    const int c0 = blockIdx.x << 5, r0 = blockIdx.y << 5;
    #pragma unroll
    for (int dy = 0; dy < 32; dy += 8) {
        t[threadIdx.y + dy][threadIdx.x] =
            in[(long)(r0 + threadIdx.y + dy) * C + c0 + threadIdx.x];
    }
    __syncthreads();
    #pragma unroll
    for (int dy = 0; dy < 32; dy += 8) {
        out[(long)(c0 + threadIdx.y + dy) * R + r0 + threadIdx.x] =
            __float2half_rn(t[threadIdx.x][threadIdx.y + dy]);
    }
}

// ---------------------------------------------------------------------------
// RMSNorm: fp32 in, half out
// ---------------------------------------------------------------------------
__global__ void rmsnorm_h(const float* __restrict__ x,
                          const float* __restrict__ g,
                          __half* __restrict__ out) {
    const int row = blockIdx.x;
    const int tid = threadIdx.x;
    const float* xr = x + (long)row * D_MODEL;
    float4 v = *reinterpret_cast<const float4*>(xr + tid * 4);
    float s = v.x * v.x + v.y * v.y + v.z * v.z + v.w * v.w;

    #pragma unroll
    for (int off = 16; off > 0; off >>= 1)
        s += __shfl_xor_sync(0xffffffffu, s, off);

    __shared__ float red[8];
    if ((tid & 31) == 0) red[tid >> 5] = s;
    __syncthreads();
    float total;
    {
        float t = (tid < 8) ? red[tid] : 0.f;
        #pragma unroll
        for (int off = 4; off > 0; off >>= 1)
            t += __shfl_xor_sync(0xffffffffu, t, off);
        __shared__ float bc;
        if (tid == 0) bc = t;
        __syncthreads();
        total = bc;
    }
    float inv = rsqrtf(total * (1.0f / D_MODEL) + 1e-6f);
    float4 gv = *reinterpret_cast<const float4*>(g + tid * 4);
    uint2 pk;
    pk.x = h2_u32(__floats2half2_rn(v.x * inv * gv.x, v.y * inv * gv.y));
    pk.y = h2_u32(__floats2half2_rn(v.z * inv * gv.z, v.w * inv * gv.w));
    *reinterpret_cast<uint2*>(out + (long)row * D_MODEL + tid * 4) = pk;
}

// ---------------------------------------------------------------------------
// RoPE in place on fused qkv (fp32, row stride 2048)
// ---------------------------------------------------------------------------
__global__ void rope_qkv(float* __restrict__ qkv) {
    const int row = blockIdx.x;
    const int t = row & (SEQ - 1);
    const int tid = threadIdx.x;

    float* ptr;
    int j;
    if (tid < 512) {                 // 16 q heads
        int h = tid >> 5; j = tid & 31;
        ptr = qkv + (long)row * QKV_N + h * HEAD_DIM;
    } else {                         // 8 k heads
        int u = tid - 512;
        int h = u >> 5; j = u & 31;
        ptr = qkv + (long)row * QKV_N + 1024 + h * HEAD_DIM;
    }
    float inv = (float)exp(-(double)j / 32.0 * 9.210340371976184);
    float fr = (float)t * inv;
    float c = cosf(fr), s = sinf(fr);
    float x1 = ptr[j], x2 = ptr[j + 32];
    ptr[j]      = x1 * c - x2 * s;
    ptr[j + 32] = x2 * c + x1 * s;
}

// ---------------------------------------------------------------------------
// Launch
// ---------------------------------------------------------------------------
extern "C" void kernel_launch(void* const* d_in, const int* in_sizes, int n_in,
                              void* d_out, int out_size) {
    const float* x  = (const float*)d_in[0];
    const float* g1 = (const float*)d_in[1];
    const float* g2 = (const float*)d_in[2];
    const float* wq = (const float*)d_in[3];
    const float* wk = (const float*)d_in[4];
    const float* wv = (const float*)d_in[5];
    const float* wo = (const float*)d_in[6];
    const float* w1 = (const float*)d_in[7];
    const float* w2 = (const float*)d_in[8];
    const float* w3 = (const float*)d_in[9];
    float* out = (float*)d_out;

    __half *h, *ao, *h2, *a, *a2, *wqkvT, *woT, *w1T, *w2T, *w3T;
    float* qkv;
    cudaGetSymbolAddress((void**)&h,   g_h);
    cudaGetSymbolAddress((void**)&qkv, g_qkv);
    cudaGetSymbolAddress((void**)&ao,  g_ao);
    cudaGetSymbolAddress((void**)&h2,  g_h2);
    cudaGetSymbolAddress((void**)&a,   g_a);
    cudaGetSymbolAddress((void**)&a2,  g_a2);
    cudaGetSymbolAddress((void**)&wqkvT, g_wqkvT);
    cudaGetSymbolAddress((void**)&woT, g_woT);
    cudaGetSymbolAddress((void**)&w1T, g_w1T);
    cudaGetSymbolAddress((void**)&w2T, g_w2T);
    cudaGetSymbolAddress((void**)&w3T, g_w3T);

    cudaFuncSetAttribute(hgemm, cudaFuncAttributeMaxDynamicSharedMemorySize,
                         GEMM_SMEM_BYTES);
    cudaFuncSetAttribute(attn_mma, cudaFuncAttributeMaxDynamicSharedMemorySize,
                         ATTN_SMEM);

    dim3 tb(32, 8);
    // weights -> half, transposed [N,K]; qkv fused into one [2048,1024]
    transpose_h<<<dim3(D_MODEL / 32, D_MODEL / 32), tb>>>(wq, wqkvT, D_MODEL, D_MODEL);
    transpose_h<<<dim3((N_KV * HEAD_DIM) / 32, D_MODEL / 32), tb>>>(wk, wqkvT + 1024 * D_MODEL, D_MODEL, N_KV * HEAD_DIM);
    transpose_h<<<dim3((N_KV * HEAD_DIM) / 32, D_MODEL / 32), tb>>>(wv, wqkvT + 1536 * D_MODEL, D_MODEL, N_KV * HEAD_DIM);
    transpose_h<<<dim3(D_MODEL / 32, D_MODEL / 32), tb>>>(wo, woT, D_MODEL, D_MODEL);
    transpose_h<<<dim3(HIDDEN / 32, D_MODEL / 32), tb>>>(w1, w1T, D_MODEL, HIDDEN);
    transpose_h<<<dim3(HIDDEN / 32, D_MODEL / 32), tb>>>(w2, w2T, D_MODEL, HIDDEN);
    transpose_h<<<dim3(D_MODEL / 32, HIDDEN / 32), tb>>>(w3, w3T, HIDDEN, D_MODEL);

    // 1. h = rmsnorm(x, g1)  (half)
    rmsnorm_h<<<BT, 256>>>(x, g1, h);

    // 2. fused qkv projection (fp16 mma, fp32 out)
    hgemm<<<dim3(QKV_N / 128, BT / 128), 128, GEMM_SMEM_BYTES>>>(
        h, wqkvT, nullptr, qkv, BT, QKV_N, D_MODEL, EPI_F32);

    // 3. RoPE in place
    rope_qkv<<<BT, 768>>>(qkv);

    // 4. attention -> ao (half)
    attn_mma<<<dim3(SEQ / 128, BATCH * N_HEADS), 128, ATTN_SMEM>>>(qkv, ao);

    // 5. out = ao @ wo + x
    hgemm<<<dim3(D_MODEL / 128, BT / 128), 128, GEMM_SMEM_BYTES>>>(
        ao, woT, x, out, BT, D_MODEL, D_MODEL, EPI_RES);

    // 6. h2 = rmsnorm(out, g2)  (half)
    rmsnorm_h<<<BT, 256>>>(out, g2, h2);

    // 7. a = h2 @ w1 (half);  a2 = silu(a) * (h2 @ w2) (half)
    hgemm<<<dim3(HIDDEN / 128, BT / 128), 128, GEMM_SMEM_BYTES>>>(
        h2, w1T, nullptr, a, BT, HIDDEN, D_MODEL, EPI_HALF);
    hgemm<<<dim3(HIDDEN / 128, BT / 128), 128, GEMM_SMEM_BYTES>>>(
        h2, w2T, a, a2, BT, HIDDEN, D_MODEL, EPI_SILU);

    // 8. out += a2 @ w3
    hgemm<<<dim3(D_MODEL / 128, BT / 128), 128, GEMM_SMEM_BYTES>>>(
        a2, w3T, out, out, BT, D_MODEL, HIDDEN, EPI_RES);
}

// round 10
// speedup vs baseline: 2.1989x; 1.2218x over previous
#include <cuda_runtime.h>
#include <cuda_fp16.h>
#include <math.h>
#include <stdint.h>

// ---------------------------------------------------------------------------
// Problem constants
// ---------------------------------------------------------------------------
#define D_MODEL   1024
#define N_HEADS   16
#define N_KV      8
#define HEAD_DIM  64
#define HIDDEN    4096
#define BATCH     4
#define SEQ       2048
#define BT        (BATCH * SEQ)
#define QKV_N     2048

// ---------------------------------------------------------------------------
// Scratch (device globals)
// ---------------------------------------------------------------------------
__device__ __half g_h  [BT * D_MODEL];
__device__ float  g_qkv[BT * QKV_N];
__device__ __half g_qh [BT * D_MODEL];
__device__ __half g_kh [BT * N_KV * HEAD_DIM];
__device__ __half g_vh [BT * N_KV * HEAD_DIM];
__device__ __half g_ao [BT * D_MODEL];
__device__ __half g_h2 [BT * D_MODEL];
__device__ __half g_a  [BT * HIDDEN];
__device__ __half g_a2 [BT * HIDDEN];

__device__ __half g_wqkvT[QKV_N * D_MODEL];
__device__ __half g_woT[D_MODEL * D_MODEL];
__device__ __half g_w1T[HIDDEN * D_MODEL];
__device__ __half g_w2T[HIDDEN * D_MODEL];
__device__ __half g_w3T[D_MODEL * HIDDEN];

// ---------------------------------------------------------------------------
// Helpers
// ---------------------------------------------------------------------------
__device__ __forceinline__ void mma_f16(float* c, const uint32_t* a, const uint32_t* b) {
    asm volatile(
        "mma.sync.aligned.m16n8k16.row.col.f32.f16.f16.f32 "
        "{%0,%1,%2,%3}, {%4,%5,%6,%7}, {%8,%9}, {%0,%1,%2,%3};\n"
        : "+f"(c[0]), "+f"(c[1]), "+f"(c[2]), "+f"(c[3])
        : "r"(a[0]), "r"(a[1]), "r"(a[2]), "r"(a[3]), "r"(b[0]), "r"(b[1]));
}
__device__ __forceinline__ void ldm_x4(uint32_t* d, uint32_t saddr) {
    asm volatile(
        "ldmatrix.sync.aligned.m8n8.x4.shared.b16 {%0,%1,%2,%3}, [%4];"
        : "=r"(d[0]), "=r"(d[1]), "=r"(d[2]), "=r"(d[3]) : "r"(saddr));
}
__device__ __forceinline__ void ldm_x4_t(uint32_t* d, uint32_t saddr) {
    asm volatile(
        "ldmatrix.sync.aligned.m8n8.x4.trans.shared.b16 {%0,%1,%2,%3}, [%4];"
        : "=r"(d[0]), "=r"(d[1]), "=r"(d[2]), "=r"(d[3]) : "r"(saddr));
}
__device__ __forceinline__ uint32_t cvta_s(const void* p) {
    return (uint32_t)__cvta_generic_to_shared(p);
}
__device__ __forceinline__ void cp16(uint32_t dst, const void* src) {
    asm volatile(
        "{ .reg .u64 g; cvta.to.global.u64 g, %1; "
        "cp.async.cg.shared.global [%0], [g], 16; }"
        :: "r"(dst), "l"(src) : "memory");
}
#define CP_COMMIT() asm volatile("cp.async.commit_group;\n" ::: "memory")
#define CP_WAIT1()  asm volatile("cp.async.wait_group 1;\n" ::: "memory")
#define CP_WAIT0()  asm volatile("cp.async.wait_group 0;\n" ::: "memory")

__device__ __forceinline__ uint32_t h2_u32(__half2 h) {
    uint32_t u;
    *reinterpret_cast<__half2*>(&u) = h;
    return u;
}

#define EPI_F32   0
#define EPI_RES   1
#define EPI_HALF  2
#define EPI_SILU  3

// ---------------------------------------------------------------------------
// fp16 tensor-core GEMM (unchanged from R8, passing)
// ---------------------------------------------------------------------------
#define BKH   32
#define LDH   40
#define STG_H (128 * LDH)
#define GEMM_SMEM_BYTES (6 * STG_H * 2)

__global__ void __launch_bounds__(128, 2)
hgemm(const __half* __restrict__ A, const __half* __restrict__ Bt,
      const void* __restrict__ Rv, void* __restrict__ Cv,
      int M, int N, int K, int epi) {
    extern __shared__ __half smh[];
    __half* Abuf[3] = { smh, smh + 2 * STG_H, smh + 4 * STG_H };
    __half* Bbuf[3] = { smh + STG_H, smh + 3 * STG_H, smh + 5 * STG_H };

    const int tid  = threadIdx.x;
    const int wid  = tid >> 5;
    const int lane = tid & 31;
    const int wm   = wid >> 1;
    const int wn   = wid & 1;
    const int gr   = lane >> 2;
    const int gc   = lane & 3;
    const int m0 = blockIdx.y << 7;
    const int n0 = blockIdx.x << 7;

    const int lr = tid >> 2;
    const int lc = (tid & 3) << 3;
    const __half* Ag = A  + (long)(m0 + lr) * K + lc;
    const __half* Bg = Bt + (long)(n0 + lr) * K + lc;

    uint32_t sA[3], sB[3], sAb[3], sBb[3];
    #pragma unroll
    for (int s = 0; s < 3; s++) {
        sAb[s] = cvta_s(Abuf[s]);
        sBb[s] = cvta_s(Bbuf[s]);
        sA[s] = cvta_s(&Abuf[s][lr * LDH + lc]);
        sB[s] = cvta_s(&Bbuf[s][lr * LDH + lc]);
    }
    const uint32_t rowstep = 32 * LDH * 2;

    const int l7  = lane & 7;
    const int sel = lane >> 3;
    const uint32_t aOff = (uint32_t)(((wm * 64 + l7 + (sel & 1) * 8) * LDH + (sel >> 1) * 8) * 2);
    const uint32_t bOff = (uint32_t)(((wn * 64 + l7 + (sel >> 1) * 8) * LDH + (sel & 1) * 8) * 2);

    const int NC = K / BKH;

    float acc[4][8][4];
    #pragma unroll
    for (int i = 0; i < 4; i++)
        #pragma unroll
        for (int j = 0; j < 8; j++)
            #pragma unroll
            for (int q = 0; q < 4; q++) acc[i][j][q] = 0.f;

    #pragma unroll
    for (int c0i = 0; c0i < 2; c0i++) {
        const long ko = (long)c0i * BKH;
        #pragma unroll
        for (int p = 0; p < 4; p++) {
            cp16(sA[c0i] + p * rowstep, Ag + (long)(p * 32) * K + ko);
            cp16(sB[c0i] + p * rowstep, Bg + (long)(p * 32) * K + ko);
        }
        CP_COMMIT();
    }

    for (int i = 0; i < NC; i++) {
        if (i < NC - 1) CP_WAIT1(); else CP_WAIT0();
        __syncthreads();

        if (i + 2 < NC) {
            const int s2 = (i + 2) % 3;
            const long ko = (long)(i + 2) * BKH;
            #pragma unroll
            for (int p = 0; p < 4; p++) {
                cp16(sA[s2] + p * rowstep, Ag + (long)(p * 32) * K + ko);
                cp16(sB[s2] + p * rowstep, Bg + (long)(p * 32) * K + ko);
            }
            CP_COMMIT();
        }

        const int cur = i % 3;
        const uint32_t aBase = sAb[cur] + aOff;
        const uint32_t bBase = sBb[cur] + bOff;

        #pragma unroll
        for (int ks = 0; ks < 2; ks++) {
            const uint32_t kb = (uint32_t)(ks * 16 * 2);
            uint32_t af[4][4], bf[8][2];
            #pragma unroll
            for (int mt = 0; mt < 4; mt++)
                ldm_x4(af[mt], aBase + (uint32_t)(mt * 16 * LDH * 2) + kb);
            #pragma unroll
            for (int np = 0; np < 4; np++) {
                uint32_t d[4];
                ldm_x4(d, bBase + (uint32_t)(np * 16 * LDH * 2) + kb);
                bf[np * 2][0]     = d[0]; bf[np * 2][1]     = d[1];
                bf[np * 2 + 1][0] = d[2]; bf[np * 2 + 1][1] = d[3];
            }
            #pragma unroll
            for (int mt = 0; mt < 4; mt++)
                #pragma unroll
                for (int nt = 0; nt < 8; nt++)
                    mma_f16(acc[mt][nt], af[mt], bf[nt]);
        }
    }
    __syncthreads();

    #pragma unroll
    for (int mt = 0; mt < 4; mt++) {
        #pragma unroll
        for (int nt = 0; nt < 8; nt++) {
            const int row = m0 + wm * 64 + mt * 16 + gr;
            const int col = n0 + wn * 64 + nt * 8 + gc * 2;
            const long offA = (long)row * N + col;
            const long offB = (long)(row + 8) * N + col;
            float2 lo = make_float2(acc[mt][nt][0], acc[mt][nt][1]);
            float2 hi = make_float2(acc[mt][nt][2], acc[mt][nt][3]);
            if (epi == EPI_F32) {
                *reinterpret_cast<float2*>((float*)Cv + offA) = lo;
                *reinterpret_cast<float2*>((float*)Cv + offB) = hi;
            } else if (epi == EPI_RES) {
                const float* R = (const float*)Rv;
                float2 r0 = *reinterpret_cast<const float2*>(R + offA);
                float2 r1 = *reinterpret_cast<const float2*>(R + offB);
                lo.x += r0.x; lo.y += r0.y;
                hi.x += r1.x; hi.y += r1.y;
                *reinterpret_cast<float2*>((float*)Cv + offA) = lo;
                *reinterpret_cast<float2*>((float*)Cv + offB) = hi;
            } else if (epi == EPI_HALF) {
                *reinterpret_cast<__half2*>((__half*)Cv + offA) = __floats2half2_rn(lo.x, lo.y);
                *reinterpret_cast<__half2*>((__half*)Cv + offB) = __floats2half2_rn(hi.x, hi.y);
            } else {
                const __half* R = (const __half*)Rv;
                float2 r0 = __half22float2(*reinterpret_cast<const __half2*>(R + offA));
                float2 r1 = __half22float2(*reinterpret_cast<const __half2*>(R + offB));
                lo.x *= r0.x / (1.0f + __expf(-r0.x));
                lo.y *= r0.y / (1.0f + __expf(-r0.y));
                hi.x *= r1.x / (1.0f + __expf(-r1.x));
                hi.y *= r1.y / (1.0f + __expf(-r1.y));
                *reinterpret_cast<__half2*>((__half*)Cv + offA) = __floats2half2_rn(lo.x, lo.y);
                *reinterpret_cast<__half2*>((__half*)Cv + offB) = __floats2half2_rn(hi.x, hi.y);
            }
        }
    }
}

// ---------------------------------------------------------------------------
// fp16 flash attention, causal GQA. (R9 design, tile-load coverage FIXED)
// ---------------------------------------------------------------------------
#define QS_LDH 72
#define KS_LDH 72
#define VS_LDH 72
#define ATTN_SMEM ((128 * QS_LDH + 2 * 64 * KS_LDH + 2 * 64 * VS_LDH) * 2)

__global__ void __launch_bounds__(128, 2)
attn_h(const __half* __restrict__ qh, const __half* __restrict__ kh,
       const __half* __restrict__ vh, __half* __restrict__ o) {
    extern __shared__ __half smh[];
    __half* Qs = smh;
    __half* Kb[2] = { smh + 128 * QS_LDH, smh + 128 * QS_LDH + 64 * KS_LDH };
    __half* Vb[2] = { Kb[1] + 64 * KS_LDH, Kb[1] + 64 * KS_LDH + 64 * VS_LDH };

    const int tid  = threadIdx.x;
    const int warp = tid >> 5;
    const int lane = tid & 31;
    const int gr = lane >> 2;
    const int gc = lane & 3;
    const int wr = warp << 5;

    const int t0  = blockIdx.x << 7;
    const int bh  = blockIdx.y;
    const int b   = bh >> 4;
    const int hq  = bh & 15;
    const int kvh = hq >> 1;

    const uint32_t qsb = cvta_s(Qs);
    uint32_t ksb[2] = { cvta_s(Kb[0]), cvta_s(Kb[1]) };
    uint32_t vsb[2] = { cvta_s(Vb[0]), cvta_s(Vb[1]) };

    const int l7  = lane & 7;
    const int sel = lane >> 3;
    const uint32_t aQoff = (uint32_t)(((wr + l7 + (sel & 1) * 8) * QS_LDH + (sel >> 1) * 8) * 2);
    const uint32_t bKoff = (uint32_t)(((l7 + (sel >> 1) * 8) * KS_LDH + (sel & 1) * 8) * 2);
    const uint32_t vToff = (uint32_t)((((sel & 1) * 8 + l7) * VS_LDH + (sel >> 1) * 8) * 2);

    // tile-load mapping: row = j>>3 (8 chunks of 8 halves per 64-half row)
    const int ldr = tid >> 3;            // 0..15 per pass of 128 threads
    const int ldc = (tid & 7) << 3;      // 0,8,...,56

    // ---- Q tile load: 128 rows x 8 chunks = 1024 slots, 8 passes ----
    {
        #pragma unroll
        for (int p = 0; p < 8; p++) {
            const int row = ldr + p * 16;
            cp16(qsb + (uint32_t)((row * QS_LDH + ldc) * 2),
                 qh + (long)(b * SEQ + t0 + row) * D_MODEL + hq * HEAD_DIM + ldc);
        }
    }
    // ---- K/V tile 0: 64 rows x 8 chunks = 512 slots, 4 passes each ----
    {
        #pragma unroll
        for (int p = 0; p < 4; p++) {
            const int row = ldr + p * 16;
            const long base = (long)(b * SEQ + row) * (N_KV * HEAD_DIM) + kvh * HEAD_DIM + ldc;
            cp16(ksb[0] + (uint32_t)((row * KS_LDH + ldc) * 2), kh + base);
            cp16(vsb[0] + (uint32_t)((row * VS_LDH + ldc) * 2), vh + base);
        }
        CP_COMMIT();
    }

    float ofrag[2][8][4];
    #pragma unroll
    for (int mt = 0; mt < 2; mt++)
        #pragma unroll
        for (int nt = 0; nt < 8; nt++)
            #pragma unroll
            for (int r = 0; r < 4; r++) ofrag[mt][nt][r] = 0.f;

    float mrow[2][2] = {{-1e30f, -1e30f}, {-1e30f, -1e30f}};
    float lrow[2][2] = {{0.f, 0.f}, {0.f, 0.f}};
    const float SC = 0.125f;

    const int ntiles = (t0 >> 6) + 2;
    for (int it = 0; it < ntiles; it++) {
        const int s0 = it << 6;
        const int cur = it & 1;

        if (it + 1 < ntiles) {
            const int nxt = cur ^ 1;
            const long roff = (long)((it + 1) << 6) * (N_KV * HEAD_DIM);
            #pragma unroll
            for (int p = 0; p < 4; p++) {
                const int row = ldr + p * 16;
                const long base = (long)(b * SEQ + row) * (N_KV * HEAD_DIM) + kvh * HEAD_DIM + ldc + roff;
                cp16(ksb[nxt] + (uint32_t)((row * KS_LDH + ldc) * 2), kh + base);
                cp16(vsb[nxt] + (uint32_t)((row * VS_LDH + ldc) * 2), vh + base);
            }
            CP_COMMIT();
            CP_WAIT1();
        } else {
            CP_WAIT0();
        }
        __syncthreads();

        // ---- S = Q @ K^T ----
        float sfrag[2][8][4];
        #pragma unroll
        for (int mt = 0; mt < 2; mt++)
            #pragma unroll
            for (int nt = 0; nt < 8; nt++)
                #pragma unroll
                for (int r = 0; r < 4; r++) sfrag[mt][nt][r] = 0.f;

        #pragma unroll
        for (int ks = 0; ks < 4; ks++) {
            const uint32_t kb = (uint32_t)(ks * 16 * 2);
            uint32_t aq[2][4], bk[8][2];
            #pragma unroll
            for (int mt = 0; mt < 2; mt++)
                ldm_x4(aq[mt], qsb + aQoff + (uint32_t)(mt * 16 * QS_LDH * 2) + kb);
            #pragma unroll
            for (int np = 0; np < 4; np++) {
                uint32_t d[4];
                ldm_x4(d, ksb[cur] + bKoff + (uint32_t)(np * 16 * KS_LDH * 2) + kb);
                bk[np * 2][0]     = d[0]; bk[np * 2][1]     = d[1];
                bk[np * 2 + 1][0] = d[2]; bk[np * 2 + 1][1] = d[3];
            }
            #pragma unroll
            for (int mt = 0; mt < 2; mt++)
                #pragma unroll
                for (int nt = 0; nt < 8; nt++)
                    mma_f16(sfrag[mt][nt], aq[mt], bk[nt]);
        }

        // ---- causal mask (diagonal tiles) ----
        if (it >= ntiles - 2) {
            #pragma unroll
            for (int mt = 0; mt < 2; mt++) {
                const int rA = t0 + wr + mt * 16 + gr;
                const int rB = rA + 8;
                #pragma unroll
                for (int nt = 0; nt < 8; nt++) {
                    const int cb = s0 + nt * 8 + 2 * gc;
                    if (cb     > rA) sfrag[mt][nt][0] = -1e30f;
                    if (cb + 1 > rA) sfrag[mt][nt][1] = -1e30f;
                    if (cb     > rB) sfrag[mt][nt][2] = -1e30f;
                    if (cb + 1 > rB) sfrag[mt][nt][3] = -1e30f;
                }
            }
        }

        // ---- online softmax ----
        #pragma unroll
        for (int mt = 0; mt < 2; mt++) {
            float r0 = -1e30f, r1 = -1e30f;
            #pragma unroll
            for (int nt = 0; nt < 8; nt++) {
                r0 = fmaxf(r0, fmaxf(sfrag[mt][nt][0], sfrag[mt][nt][1]));
                r1 = fmaxf(r1, fmaxf(sfrag[mt][nt][2], sfrag[mt][nt][3]));
            }
            r0 = fmaxf(r0, __shfl_xor_sync(0xffffffffu, r0, 1));
            r0 = fmaxf(r0, __shfl_xor_sync(0xffffffffu, r0, 2));
            r1 = fmaxf(r1, __shfl_xor_sync(0xffffffffu, r1, 1));
            r1 = fmaxf(r1, __shfl_xor_sync(0xffffffffu, r1, 2));

            const float mn0 = fmaxf(mrow[mt][0], r0);
            const float mn1 = fmaxf(mrow[mt][1], r1);
            const float c0 = __expf((mrow[mt][0] - mn0) * SC);
            const float c1 = __expf((mrow[mt][1] - mn1) * SC);
            lrow[mt][0] *= c0;
            lrow[mt][1] *= c1;
            #pragma unroll
            for (int nt = 0; nt < 8; nt++) {
                ofrag[mt][nt][0] *= c0; ofrag[mt][nt][1] *= c0;
                ofrag[mt][nt][2] *= c1; ofrag[mt][nt][3] *= c1;
            }
            float s0s = 0.f, s1s = 0.f;
            #pragma unroll
            for (int nt = 0; nt < 8; nt++) {
                sfrag[mt][nt][0] = __expf((sfrag[mt][nt][0] - mn0) * SC);
                sfrag[mt][nt][1] = __expf((sfrag[mt][nt][1] - mn0) * SC);
                sfrag[mt][nt][2] = __expf((sfrag[mt][nt][2] - mn1) * SC);
                sfrag[mt][nt][3] = __expf((sfrag[mt][nt][3] - mn1) * SC);
                s0s += sfrag[mt][nt][0] + sfrag[mt][nt][1];
                s1s += sfrag[mt][nt][2] + sfrag[mt][nt][3];
            }
            s0s += __shfl_xor_sync(0xffffffffu, s0s, 1);
            s0s += __shfl_xor_sync(0xffffffffu, s0s, 2);
            s1s += __shfl_xor_sync(0xffffffffu, s1s, 1);
            s1s += __shfl_xor_sync(0xffffffffu, s1s, 2);
            lrow[mt][0] += s0s;
            lrow[mt][1] += s1s;
            mrow[mt][0] = mn0;
            mrow[mt][1] = mn1;
        }

        // ---- O += P @ V  (P C-frag layout == fp16 A-frag layout) ----
        #pragma unroll
        for (int ks = 0; ks < 4; ks++) {
            uint32_t ap[2][4];
            #pragma unroll
            for (int mt = 0; mt < 2; mt++) {
                ap[mt][0] = h2_u32(__floats2half2_rn(sfrag[mt][2 * ks][0],     sfrag[mt][2 * ks][1]));
                ap[mt][1] = h2_u32(__floats2half2_rn(sfrag[mt][2 * ks][2],     sfrag[mt][2 * ks][3]));
                ap[mt][2] = h2_u32(__floats2half2_rn(sfrag[mt][2 * ks + 1][0], sfrag[mt][2 * ks + 1][1]));
                ap[mt][3] = h2_u32(__floats2half2_rn(sfrag[mt][2 * ks + 1][2], sfrag[mt][2 * ks + 1][3]));
            }
            uint32_t bv[8][2];
            #pragma unroll
            for (int np = 0; np < 4; np++) {
                uint32_t d[4];
                ldm_x4_t(d, vsb[cur] + vToff +
                            (uint32_t)((ks * 16 * VS_LDH + np * 16) * 2));
                bv[np * 2][0]     = d[0]; bv[np * 2][1]     = d[1];
                bv[np * 2 + 1][0] = d[2]; bv[np * 2 + 1][1] = d[3];
            }
            #pragma unroll
            for (int mt = 0; mt < 2; mt++)
                #pragma unroll
                for (int nt = 0; nt < 8; nt++)
                    mma_f16(ofrag[mt][nt], ap[mt], bv[nt]);
        }
        __syncthreads();
    }

    // ---- write O (half) ----
    #pragma unroll
    for (int mt = 0; mt < 2; mt++) {
        const int rowA = t0 + wr + mt * 16 + gr;
        const int rowB = rowA + 8;
        const float il0 = 1.0f / lrow[mt][0];
        const float il1 = 1.0f / lrow[mt][1];
        #pragma unroll
        for (int nt = 0; nt < 8; nt++) {
            const int col = hq * HEAD_DIM + nt * 8 + 2 * gc;
            *reinterpret_cast<__half2*>(o + (long)(b * SEQ + rowA) * D_MODEL + col) =
                __floats2half2_rn(ofrag[mt][nt][0] * il0, ofrag[mt][nt][1] * il0);
            *reinterpret_cast<__half2*>(o + (long)(b * SEQ + rowB) * D_MODEL + col) =
                __floats2half2_rn(ofrag[mt][nt][2] * il1, ofrag[mt][nt][3] * il1);
        }
    }
}

// ---------------------------------------------------------------------------
// Transpose to half
// ---------------------------------------------------------------------------
__global__ void transpose_h(const float* __restrict__ in,
                            __half* __restrict__ out, int R, int C) {
    __shared__ float t[32][33];
    const int c0 = blockIdx.x << 5, r0 = blockIdx.y << 5;
    #pragma unroll
    for (int dy = 0; dy < 32; dy += 8) {
        t[threadIdx.y + dy][threadIdx.x] =
            in[(long)(r0 + threadIdx.y + dy) * C + c0 + threadIdx.x];
    }
    __syncthreads();
    #pragma unroll
    for (int dy = 0; dy < 32; dy += 8) {
        out[(long)(c0 + threadIdx.y + dy) * R + r0 + threadIdx.x] =
            __float2half_rn(t[threadIdx.x][threadIdx.y + dy]);
    }
}

// ---------------------------------------------------------------------------
// RMSNorm: fp32 in, half out
// ---------------------------------------------------------------------------
__global__ void rmsnorm_h(const float* __restrict__ x,
                          const float* __restrict__ g,
                          __half* __restrict__ out) {
    const int row = blockIdx.x;
    const int tid = threadIdx.x;
    const float* xr = x + (long)row * D_MODEL;
    float4 v = *reinterpret_cast<const float4*>(xr + tid * 4);
    float s = v.x * v.x + v.y * v.y + v.z * v.z + v.w * v.w;

    #pragma unroll
    for (int off = 16; off > 0; off >>= 1)
        s += __shfl_xor_sync(0xffffffffu, s, off);

    __shared__ float red[8];
    if ((tid & 31) == 0) red[tid >> 5] = s;
    __syncthreads();
    float total;
    {
        float t = (tid < 8) ? red[tid] : 0.f;
        #pragma unroll
        for (int off = 4; off > 0; off >>= 1)
            t += __shfl_xor_sync(0xffffffffu, t, off);
        __shared__ float bc;
        if (tid == 0) bc = t;
        __syncthreads();
        total = bc;
    }
    float inv = rsqrtf(total * (1.0f / D_MODEL) + 1e-6f);
    float4 gv = *reinterpret_cast<const float4*>(g + tid * 4);
    uint2 pk;
    pk.x = h2_u32(__floats2half2_rn(v.x * inv * gv.x, v.y * inv * gv.y));
    pk.y = h2_u32(__floats2half2_rn(v.z * inv * gv.z, v.w * inv * gv.w));
    *reinterpret_cast<uint2*>(out + (long)row * D_MODEL + tid * 4) = pk;
}

// ---------------------------------------------------------------------------
// RoPE: fp32 qkv in, half q/k/v out
// ---------------------------------------------------------------------------
__global__ void rope_h(const float* __restrict__ qkv,
                       __half* __restrict__ qh, __half* __restrict__ kh,
                       __half* __restrict__ vh) {
    const int row = blockIdx.x;
    const int t = row & (SEQ - 1);
    const int tid = threadIdx.x;
    const float* src = qkv + (long)row * QKV_N;

    if (tid < 768) {
        const float* p;
        __half* dst;
        int j, base;
        if (tid < 512) {
            int h = tid >> 5; j = tid & 31;
            base = h * HEAD_DIM;
            p = src + base;
            dst = qh + (long)row * D_MODEL + base;
        } else {
            int u = tid - 512;
            int h = u >> 5; j = u & 31;
            base = h * HEAD_DIM;
            p = src + 1024 + base;
            dst = kh + (long)row * (N_KV * HEAD_DIM) + base;
        }
        float inv = (float)exp(-(double)j / 32.0 * 9.210340371976184);
        float fr = (float)t * inv;
        float c = cosf(fr), s = sinf(fr);
        float x1 = p[j], x2 = p[j + 32];
        dst[j]      = __float2half_rn(x1 * c - x2 * s);
        dst[j + 32] = __float2half_rn(x2 * c + x1 * s);
    } else {
        int u = (tid - 768) << 1;
        float2 vv = *reinterpret_cast<const float2*>(src + 1536 + u);
        *reinterpret_cast<__half2*>(vh + (long)row * (N_KV * HEAD_DIM) + u) =
            __floats2half2_rn(vv.x, vv.y);
    }
}

// ---------------------------------------------------------------------------
// Launch
// ---------------------------------------------------------------------------
extern "C" void kernel_launch(void* const* d_in, const int* in_sizes, int n_in,
                              void* d_out, int out_size) {
    const float* x  = (const float*)d_in[0];
    const float* g1 = (const float*)d_in[1];
    const float* g2 = (const float*)d_in[2];
    const float* wq = (const float*)d_in[3];
    const float* wk = (const float*)d_in[4];
    const float* wv = (const float*)d_in[5];
    const float* wo = (const float*)d_in[6];
    const float* w1 = (const float*)d_in[7];
    const float* w2 = (const float*)d_in[8];
    const float* w3 = (const float*)d_in[9];
    float* out = (float*)d_out;

    __half *h, *qh, *kh, *vh, *ao, *h2, *a, *a2;
    __half *wqkvT, *woT, *w1T, *w2T, *w3T;
    float* qkv;
    cudaGetSymbolAddress((void**)&h,   g_h);
    cudaGetSymbolAddress((void**)&qkv, g_qkv);
    cudaGetSymbolAddress((void**)&qh,  g_qh);
    cudaGetSymbolAddress((void**)&kh,  g_kh);
    cudaGetSymbolAddress((void**)&vh,  g_vh);
    cudaGetSymbolAddress((void**)&ao,  g_ao);
    cudaGetSymbolAddress((void**)&h2,  g_h2);
    cudaGetSymbolAddress((void**)&a,   g_a);
    cudaGetSymbolAddress((void**)&a2,  g_a2);
    cudaGetSymbolAddress((void**)&wqkvT, g_wqkvT);
    cudaGetSymbolAddress((void**)&woT, g_woT);
    cudaGetSymbolAddress((void**)&w1T, g_w1T);
    cudaGetSymbolAddress((void**)&w2T, g_w2T);
    cudaGetSymbolAddress((void**)&w3T, g_w3T);

    cudaFuncSetAttribute(hgemm, cudaFuncAttributeMaxDynamicSharedMemorySize,
                         GEMM_SMEM_BYTES);
    cudaFuncSetAttribute(attn_h, cudaFuncAttributeMaxDynamicSharedMemorySize,
                         ATTN_SMEM);

    dim3 tb(32, 8);
    transpose_h<<<dim3(D_MODEL / 32, D_MODEL / 32), tb>>>(wq, wqkvT, D_MODEL, D_MODEL);
    transpose_h<<<dim3((N_KV * HEAD_DIM) / 32, D_MODEL / 32), tb>>>(wk, wqkvT + 1024 * D_MODEL, D_MODEL, N_KV * HEAD_DIM);
    transpose_h<<<dim3((N_KV * HEAD_DIM) / 32, D_MODEL / 32), tb>>>(wv, wqkvT + 1536 * D_MODEL, D_MODEL, N_KV * HEAD_DIM);
    transpose_h<<<dim3(D_MODEL / 32, D_MODEL / 32), tb>>>(wo, woT, D_MODEL, D_MODEL);
    transpose_h<<<dim3(HIDDEN / 32, D_MODEL / 32), tb>>>(w1, w1T, D_MODEL, HIDDEN);
    transpose_h<<<dim3(HIDDEN / 32, D_MODEL / 32), tb>>>(w2, w2T, D_MODEL, HIDDEN);
    transpose_h<<<dim3(D_MODEL / 32, HIDDEN / 32), tb>>>(w3, w3T, HIDDEN, D_MODEL);

    rmsnorm_h<<<BT, 256>>>(x, g1, h);

    hgemm<<<dim3(QKV_N / 128, BT / 128), 128, GEMM_SMEM_BYTES>>>(
        h, wqkvT, nullptr, qkv, BT, QKV_N, D_MODEL, EPI_F32);

    rope_h<<<BT, 1024>>>(qkv, qh, kh, vh);

    attn_h<<<dim3(SEQ / 128, BATCH * N_HEADS), 128, ATTN_SMEM>>>(qh, kh, vh, ao);

    hgemm<<<dim3(D_MODEL / 128, BT / 128), 128, GEMM_SMEM_BYTES>>>(
        ao, woT, x, out, BT, D_MODEL, D_MODEL, EPI_RES);

    rmsnorm_h<<<BT, 256>>>(out, g2, h2);

    hgemm<<<dim3(HIDDEN / 128, BT / 128), 128, GEMM_SMEM_BYTES>>>(
        h2, w1T, nullptr, a, BT, HIDDEN, D_MODEL, EPI_HALF);
    hgemm<<<dim3(HIDDEN / 128, BT / 128), 128, GEMM_SMEM_BYTES>>>(
        h2, w2T, a, a2, BT, HIDDEN, D_MODEL, EPI_SILU);

    hgemm<<<dim3(D_MODEL / 128, BT / 128), 128, GEMM_SMEM_BYTES>>>(
        a2, w3T, out, out, BT, D_MODEL, HIDDEN, EPI_RES);
}

// round 11
// speedup vs baseline: 2.6483x; 1.2043x over previous
#include <cuda_runtime.h>
#include <cuda_fp16.h>
#include <math.h>
#include <stdint.h>

// ---------------------------------------------------------------------------
// Problem constants
// ---------------------------------------------------------------------------
#define D_MODEL   1024
#define N_HEADS   16
#define N_KV      8
#define HEAD_DIM  64
#define HIDDEN    4096
#define BATCH     4
#define SEQ       2048
#define BT        (BATCH * SEQ)
#define QKV_N     2048

// ---------------------------------------------------------------------------
// Scratch (device globals)
// ---------------------------------------------------------------------------
__device__ __half g_h  [BT * D_MODEL];
__device__ __half g_qh [BT * D_MODEL];
__device__ __half g_kh [BT * N_KV * HEAD_DIM];
__device__ __half g_vh [BT * N_KV * HEAD_DIM];
__device__ __half g_ao [BT * D_MODEL];
__device__ __half g_h2 [BT * D_MODEL];
__device__ __half g_a  [BT * HIDDEN];
__device__ __half g_a2 [BT * HIDDEN];
__device__ float2 g_rope[SEQ * 32];             // (cos,sin) per (t, j)

__device__ __half g_wqkvT[QKV_N * D_MODEL];
__device__ __half g_woT[D_MODEL * D_MODEL];
__device__ __half g_w1T[HIDDEN * D_MODEL];
__device__ __half g_w2T[HIDDEN * D_MODEL];
__device__ __half g_w3T[D_MODEL * HIDDEN];

// ---------------------------------------------------------------------------
// Helpers
// ---------------------------------------------------------------------------
__device__ __forceinline__ void mma_f16(float* c, const uint32_t* a, const uint32_t* b) {
    asm volatile(
        "mma.sync.aligned.m16n8k16.row.col.f32.f16.f16.f32 "
        "{%0,%1,%2,%3}, {%4,%5,%6,%7}, {%8,%9}, {%0,%1,%2,%3};\n"
        : "+f"(c[0]), "+f"(c[1]), "+f"(c[2]), "+f"(c[3])
        : "r"(a[0]), "r"(a[1]), "r"(a[2]), "r"(a[3]), "r"(b[0]), "r"(b[1]));
}
__device__ __forceinline__ void ldm_x4(uint32_t* d, uint32_t saddr) {
    asm volatile(
        "ldmatrix.sync.aligned.m8n8.x4.shared.b16 {%0,%1,%2,%3}, [%4];"
        : "=r"(d[0]), "=r"(d[1]), "=r"(d[2]), "=r"(d[3]) : "r"(saddr));
}
__device__ __forceinline__ void ldm_x4_t(uint32_t* d, uint32_t saddr) {
    asm volatile(
        "ldmatrix.sync.aligned.m8n8.x4.trans.shared.b16 {%0,%1,%2,%3}, [%4];"
        : "=r"(d[0]), "=r"(d[1]), "=r"(d[2]), "=r"(d[3]) : "r"(saddr));
}
__device__ __forceinline__ uint32_t cvta_s(const void* p) {
    return (uint32_t)__cvta_generic_to_shared(p);
}
__device__ __forceinline__ void cp16(uint32_t dst, const void* src) {
    asm volatile(
        "{ .reg .u64 g; cvta.to.global.u64 g, %1; "
        "cp.async.cg.shared.global [%0], [g], 16; }"
        :: "r"(dst), "l"(src) : "memory");
}
#define CP_COMMIT() asm volatile("cp.async.commit_group;\n" ::: "memory")
#define CP_WAIT1()  asm volatile("cp.async.wait_group 1;\n" ::: "memory")
#define CP_WAIT0()  asm volatile("cp.async.wait_group 0;\n" ::: "memory")

__device__ __forceinline__ uint32_t h2_u32(__half2 h) {
    uint32_t u;
    *reinterpret_cast<__half2*>(&u) = h;
    return u;
}

#define EPI_RES   1
#define EPI_HALF  2
#define EPI_SILU  3
#define EPI_ROPE  4   // fused rope + half q/k/v outputs (QKV GEMM only)

// ---------------------------------------------------------------------------
// fp16 tensor-core GEMM; mainloop unchanged from R10 (passing)
// ---------------------------------------------------------------------------
#define BKH   32
#define LDH   40
#define STG_H (128 * LDH)
#define GEMM_SMEM_BYTES (6 * STG_H * 2)

__global__ void __launch_bounds__(128, 2)
hgemm(const __half* __restrict__ A, const __half* __restrict__ Bt,
      const void* __restrict__ Rv, void* __restrict__ Cv,
      int M, int N, int K, int epi,
      __half* __restrict__ q_out, __half* __restrict__ k_out,
      __half* __restrict__ v_out, const float2* __restrict__ rope_tab) {
    extern __shared__ __half smh[];
    __half* Abuf[3] = { smh, smh + 2 * STG_H, smh + 4 * STG_H };
    __half* Bbuf[3] = { smh + STG_H, smh + 3 * STG_H, smh + 5 * STG_H };

    const int tid  = threadIdx.x;
    const int wid  = tid >> 5;
    const int lane = tid & 31;
    const int wm   = wid >> 1;
    const int wn   = wid & 1;
    const int gr   = lane >> 2;
    const int gc   = lane & 3;
    const int m0 = blockIdx.y << 7;
    const int n0 = blockIdx.x << 7;

    const int lr = tid >> 2;
    const int lc = (tid & 3) << 3;
    const __half* Ag = A  + (long)(m0 + lr) * K + lc;
    const __half* Bg = Bt + (long)(n0 + lr) * K + lc;

    uint32_t sA[3], sB[3], sAb[3], sBb[3];
    #pragma unroll
    for (int s = 0; s < 3; s++) {
        sAb[s] = cvta_s(Abuf[s]);
        sBb[s] = cvta_s(Bbuf[s]);
        sA[s] = cvta_s(&Abuf[s][lr * LDH + lc]);
        sB[s] = cvta_s(&Bbuf[s][lr * LDH + lc]);
    }
    const uint32_t rowstep = 32 * LDH * 2;

    const int l7  = lane & 7;
    const int sel = lane >> 3;
    const uint32_t aOff = (uint32_t)(((wm * 64 + l7 + (sel & 1) * 8) * LDH + (sel >> 1) * 8) * 2);
    const uint32_t bOff = (uint32_t)(((wn * 64 + l7 + (sel >> 1) * 8) * LDH + (sel & 1) * 8) * 2);

    const int NC = K / BKH;

    float acc[4][8][4];
    #pragma unroll
    for (int i = 0; i < 4; i++)
        #pragma unroll
        for (int j = 0; j < 8; j++)
            #pragma unroll
            for (int q = 0; q < 4; q++) acc[i][j][q] = 0.f;

    #pragma unroll
    for (int c0i = 0; c0i < 2; c0i++) {
        const long ko = (long)c0i * BKH;
        #pragma unroll
        for (int p = 0; p < 4; p++) {
            cp16(sA[c0i] + p * rowstep, Ag + (long)(p * 32) * K + ko);
            cp16(sB[c0i] + p * rowstep, Bg + (long)(p * 32) * K + ko);
        }
        CP_COMMIT();
    }

    for (int i = 0; i < NC; i++) {
        if (i < NC - 1) CP_WAIT1(); else CP_WAIT0();
        __syncthreads();

        if (i + 2 < NC) {
            const int s2 = (i + 2) % 3;
            const long ko = (long)(i + 2) * BKH;
            #pragma unroll
            for (int p = 0; p < 4; p++) {
                cp16(sA[s2] + p * rowstep, Ag + (long)(p * 32) * K + ko);
                cp16(sB[s2] + p * rowstep, Bg + (long)(p * 32) * K + ko);
            }
            CP_COMMIT();
        }

        const int cur = i % 3;
        const uint32_t aBase = sAb[cur] + aOff;
        const uint32_t bBase = sBb[cur] + bOff;

        #pragma unroll
        for (int ks = 0; ks < 2; ks++) {
            const uint32_t kb = (uint32_t)(ks * 16 * 2);
            uint32_t af[4][4], bf[8][2];
            #pragma unroll
            for (int mt = 0; mt < 4; mt++)
                ldm_x4(af[mt], aBase + (uint32_t)(mt * 16 * LDH * 2) + kb);
            #pragma unroll
            for (int np = 0; np < 4; np++) {
                uint32_t d[4];
                ldm_x4(d, bBase + (uint32_t)(np * 16 * LDH * 2) + kb);
                bf[np * 2][0]     = d[0]; bf[np * 2][1]     = d[1];
                bf[np * 2 + 1][0] = d[2]; bf[np * 2 + 1][1] = d[3];
            }
            #pragma unroll
            for (int mt = 0; mt < 4; mt++)
                #pragma unroll
                for (int nt = 0; nt < 8; nt++)
                    mma_f16(acc[mt][nt], af[mt], bf[nt]);
        }
    }
    __syncthreads();

    // ---------------- epilogues ----------------
    if (epi == EPI_ROPE) {
        // warp tile = exactly one head (64 cols). head 0-15: q, 16-23: k, 24-31: v
        const int head = (n0 + wn * 64) >> 6;
        #pragma unroll
        for (int mt = 0; mt < 4; mt++) {
            const int rowA = m0 + wm * 64 + mt * 16 + gr;
            const int rowB = rowA + 8;
            const int tA = rowA & (SEQ - 1);
            const int tB = rowB & (SEQ - 1);
            if (head < 24) {
                __half* dstA;
                long stride;
                if (head < 16) {
                    dstA = q_out + (long)rowA * D_MODEL + head * HEAD_DIM;
                    stride = D_MODEL;
                } else {
                    dstA = k_out + (long)rowA * (N_KV * HEAD_DIM) + (head - 16) * HEAD_DIM;
                    stride = N_KV * HEAD_DIM;
                }
                __half* dstB = dstA + 8 * stride;
                #pragma unroll
                for (int nt = 0; nt < 4; nt++) {
                    const int j0 = nt * 8 + gc * 2;
                    const float2 cA0 = rope_tab[tA * 32 + j0];
                    const float2 cA1 = rope_tab[tA * 32 + j0 + 1];
                    const float2 cB0 = rope_tab[tB * 32 + j0];
                    const float2 cB1 = rope_tab[tB * 32 + j0 + 1];
                    const float x1a0 = acc[mt][nt][0],     x1a1 = acc[mt][nt][1];
                    const float x1b0 = acc[mt][nt][2],     x1b1 = acc[mt][nt][3];
                    const float x2a0 = acc[mt][nt + 4][0], x2a1 = acc[mt][nt + 4][1];
                    const float x2b0 = acc[mt][nt + 4][2], x2b1 = acc[mt][nt + 4][3];
                    *reinterpret_cast<__half2*>(dstA + j0) =
                        __floats2half2_rn(x1a0 * cA0.x - x2a0 * cA0.y,
                                          x1a1 * cA1.x - x2a1 * cA1.y);
                    *reinterpret_cast<__half2*>(dstA + j0 + 32) =
                        __floats2half2_rn(x2a0 * cA0.x + x1a0 * cA0.y,
                                          x2a1 * cA1.x + x1a1 * cA1.y);
                    *reinterpret_cast<__half2*>(dstB + j0) =
                        __floats2half2_rn(x1b0 * cB0.x - x2b0 * cB0.y,
                                          x1b1 * cB1.x - x2b1 * cB1.y);
                    *reinterpret_cast<__half2*>(dstB + j0 + 32) =
                        __floats2half2_rn(x2b0 * cB0.x + x1b0 * cB0.y,
                                          x2b1 * cB1.x + x1b1 * cB1.y);
                }
            } else {
                __half* dstA = v_out + (long)rowA * (N_KV * HEAD_DIM) + (head - 24) * HEAD_DIM;
                __half* dstB = dstA + 8 * (N_KV * HEAD_DIM);
                #pragma unroll
                for (int nt = 0; nt < 8; nt++) {
                    const int c = nt * 8 + gc * 2;
                    *reinterpret_cast<__half2*>(dstA + c) =
                        __floats2half2_rn(acc[mt][nt][0], acc[mt][nt][1]);
                    *reinterpret_cast<__half2*>(dstB + c) =
                        __floats2half2_rn(acc[mt][nt][2], acc[mt][nt][3]);
                }
            }
        }
        return;
    }

    #pragma unroll
    for (int mt = 0; mt < 4; mt++) {
        #pragma unroll
        for (int nt = 0; nt < 8; nt++) {
            const int row = m0 + wm * 64 + mt * 16 + gr;
            const int col = n0 + wn * 64 + nt * 8 + gc * 2;
            const long offA = (long)row * N + col;
            const long offB = (long)(row + 8) * N + col;
            float2 lo = make_float2(acc[mt][nt][0], acc[mt][nt][1]);
            float2 hi = make_float2(acc[mt][nt][2], acc[mt][nt][3]);
            if (epi == EPI_RES) {
                const float* R = (const float*)Rv;
                float2 r0 = *reinterpret_cast<const float2*>(R + offA);
                float2 r1 = *reinterpret_cast<const float2*>(R + offB);
                lo.x += r0.x; lo.y += r0.y;
                hi.x += r1.x; hi.y += r1.y;
                *reinterpret_cast<float2*>((float*)Cv + offA) = lo;
                *reinterpret_cast<float2*>((float*)Cv + offB) = hi;
            } else if (epi == EPI_HALF) {
                *reinterpret_cast<__half2*>((__half*)Cv + offA) = __floats2half2_rn(lo.x, lo.y);
                *reinterpret_cast<__half2*>((__half*)Cv + offB) = __floats2half2_rn(hi.x, hi.y);
            } else {  // EPI_SILU
                const __half* R = (const __half*)Rv;
                float2 r0 = __half22float2(*reinterpret_cast<const __half2*>(R + offA));
                float2 r1 = __half22float2(*reinterpret_cast<const __half2*>(R + offB));
                lo.x *= r0.x / (1.0f + __expf(-r0.x));
                lo.y *= r0.y / (1.0f + __expf(-r0.y));
                hi.x *= r1.x / (1.0f + __expf(-r1.x));
                hi.y *= r1.y / (1.0f + __expf(-r1.y));
                *reinterpret_cast<__half2*>((__half*)Cv + offA) = __floats2half2_rn(lo.x, lo.y);
                *reinterpret_cast<__half2*>((__half*)Cv + offB) = __floats2half2_rn(hi.x, hi.y);
            }
        }
    }
}

// ---------------------------------------------------------------------------
// fp16 flash attention, causal GQA (unchanged from R10, passing)
// ---------------------------------------------------------------------------
#define QS_LDH 72
#define KS_LDH 72
#define VS_LDH 72
#define ATTN_SMEM ((128 * QS_LDH + 2 * 64 * KS_LDH + 2 * 64 * VS_LDH) * 2)

__global__ void __launch_bounds__(128, 2)
attn_h(const __half* __restrict__ qh, const __half* __restrict__ kh,
       const __half* __restrict__ vh, __half* __restrict__ o) {
    extern __shared__ __half smh[];
    __half* Qs = smh;
    __half* Kb[2] = { smh + 128 * QS_LDH, smh + 128 * QS_LDH + 64 * KS_LDH };
    __half* Vb[2] = { Kb[1] + 64 * KS_LDH, Kb[1] + 64 * KS_LDH + 64 * VS_LDH };

    const int tid  = threadIdx.x;
    const int warp = tid >> 5;
    const int lane = tid & 31;
    const int gr = lane >> 2;
    const int gc = lane & 3;
    const int wr = warp << 5;

    const int t0  = blockIdx.x << 7;
    const int bh  = blockIdx.y;
    const int b   = bh >> 4;
    const int hq  = bh & 15;
    const int kvh = hq >> 1;

    const uint32_t qsb = cvta_s(Qs);
    uint32_t ksb[2] = { cvta_s(Kb[0]), cvta_s(Kb[1]) };
    uint32_t vsb[2] = { cvta_s(Vb[0]), cvta_s(Vb[1]) };

    const int l7  = lane & 7;
    const int sel = lane >> 3;
    const uint32_t aQoff = (uint32_t)(((wr + l7 + (sel & 1) * 8) * QS_LDH + (sel >> 1) * 8) * 2);
    const uint32_t bKoff = (uint32_t)(((l7 + (sel >> 1) * 8) * KS_LDH + (sel & 1) * 8) * 2);
    const uint32_t vToff = (uint32_t)((((sel & 1) * 8 + l7) * VS_LDH + (sel >> 1) * 8) * 2);

    const int ldr = tid >> 3;
    const int ldc = (tid & 7) << 3;

    {
        #pragma unroll
        for (int p = 0; p < 8; p++) {
            const int row = ldr + p * 16;
            cp16(qsb + (uint32_t)((row * QS_LDH + ldc) * 2),
                 qh + (long)(b * SEQ + t0 + row) * D_MODEL + hq * HEAD_DIM + ldc);
        }
    }
    {
        #pragma unroll
        for (int p = 0; p < 4; p++) {
            const int row = ldr + p * 16;
            const long base = (long)(b * SEQ + row) * (N_KV * HEAD_DIM) + kvh * HEAD_DIM + ldc;
            cp16(ksb[0] + (uint32_t)((row * KS_LDH + ldc) * 2), kh + base);
            cp16(vsb[0] + (uint32_t)((row * VS_LDH + ldc) * 2), vh + base);
        }
        CP_COMMIT();
    }

    float ofrag[2][8][4];
    #pragma unroll
    for (int mt = 0; mt < 2; mt++)
        #pragma unroll
        for (int nt = 0; nt < 8; nt++)
            #pragma unroll
            for (int r = 0; r < 4; r++) ofrag[mt][nt][r] = 0.f;

    float mrow[2][2] = {{-1e30f, -1e30f}, {-1e30f, -1e30f}};
    float lrow[2][2] = {{0.f, 0.f}, {0.f, 0.f}};
    const float SC = 0.125f;

    const int ntiles = (t0 >> 6) + 2;
    for (int it = 0; it < ntiles; it++) {
        const int s0 = it << 6;
        const int cur = it & 1;

        if (it + 1 < ntiles) {
            const int nxt = cur ^ 1;
            const long roff = (long)((it + 1) << 6) * (N_KV * HEAD_DIM);
            #pragma unroll
            for (int p = 0; p < 4; p++) {
                const int row = ldr + p * 16;
                const long base = (long)(b * SEQ + row) * (N_KV * HEAD_DIM) + kvh * HEAD_DIM + ldc + roff;
                cp16(ksb[nxt] + (uint32_t)((row * KS_LDH + ldc) * 2), kh + base);
                cp16(vsb[nxt] + (uint32_t)((row * VS_LDH + ldc) * 2), vh + base);
            }
            CP_COMMIT();
            CP_WAIT1();
        } else {
            CP_WAIT0();
        }
        __syncthreads();

        float sfrag[2][8][4];
        #pragma unroll
        for (int mt = 0; mt < 2; mt++)
            #pragma unroll
            for (int nt = 0; nt < 8; nt++)
                #pragma unroll
                for (int r = 0; r < 4; r++) sfrag[mt][nt][r] = 0.f;

        #pragma unroll
        for (int ks = 0; ks < 4; ks++) {
            const uint32_t kb = (uint32_t)(ks * 16 * 2);
            uint32_t aq[2][4], bk[8][2];
            #pragma unroll
            for (int mt = 0; mt < 2; mt++)
                ldm_x4(aq[mt], qsb + aQoff + (uint32_t)(mt * 16 * QS_LDH * 2) + kb);
            #pragma unroll
            for (int np = 0; np < 4; np++) {
                uint32_t d[4];
                ldm_x4(d, ksb[cur] + bKoff + (uint32_t)(np * 16 * KS_LDH * 2) + kb);
                bk[np * 2][0]     = d[0]; bk[np * 2][1]     = d[1];
                bk[np * 2 + 1][0] = d[2]; bk[np * 2 + 1][1] = d[3];
            }
            #pragma unroll
            for (int mt = 0; mt < 2; mt++)
                #pragma unroll
                for (int nt = 0; nt < 8; nt++)
                    mma_f16(sfrag[mt][nt], aq[mt], bk[nt]);
        }

        if (it >= ntiles - 2) {
            #pragma unroll
            for (int mt = 0; mt < 2; mt++) {
                const int rA = t0 + wr + mt * 16 + gr;
                const int rB = rA + 8;
                #pragma unroll
                for (int nt = 0; nt < 8; nt++) {
                    const int cb = s0 + nt * 8 + 2 * gc;
                    if (cb     > rA) sfrag[mt][nt][0] = -1e30f;
                    if (cb + 1 > rA) sfrag[mt][nt][1] = -1e30f;
                    if (cb     > rB) sfrag[mt][nt][2] = -1e30f;
                    if (cb + 1 > rB) sfrag[mt][nt][3] = -1e30f;
                }
            }
        }

        #pragma unroll
        for (int mt = 0; mt < 2; mt++) {
            float r0 = -1e30f, r1 = -1e30f;
            #pragma unroll
            for (int nt = 0; nt < 8; nt++) {
                r0 = fmaxf(r0, fmaxf(sfrag[mt][nt][0], sfrag[mt][nt][1]));
                r1 = fmaxf(r1, fmaxf(sfrag[mt][nt][2], sfrag[mt][nt][3]));
            }
            r0 = fmaxf(r0, __shfl_xor_sync(0xffffffffu, r0, 1));
            r0 = fmaxf(r0, __shfl_xor_sync(0xffffffffu, r0, 2));
            r1 = fmaxf(r1, __shfl_xor_sync(0xffffffffu, r1, 1));
            r1 = fmaxf(r1, __shfl_xor_sync(0xffffffffu, r1, 2));

            const float mn0 = fmaxf(mrow[mt][0], r0);
            const float mn1 = fmaxf(mrow[mt][1], r1);
            const float c0 = __expf((mrow[mt][0] - mn0) * SC);
            const float c1 = __expf((mrow[mt][1] - mn1) * SC);
            lrow[mt][0] *= c0;
            lrow[mt][1] *= c1;
            #pragma unroll
            for (int nt = 0; nt < 8; nt++) {
                ofrag[mt][nt][0] *= c0; ofrag[mt][nt][1] *= c0;
                ofrag[mt][nt][2] *= c1; ofrag[mt][nt][3] *= c1;
            }
            float s0s = 0.f, s1s = 0.f;
            #pragma unroll
            for (int nt = 0; nt < 8; nt++) {
                sfrag[mt][nt][0] = __expf((sfrag[mt][nt][0] - mn0) * SC);
                sfrag[mt][nt][1] = __expf((sfrag[mt][nt][1] - mn0) * SC);
                sfrag[mt][nt][2] = __expf((sfrag[mt][nt][2] - mn1) * SC);
                sfrag[mt][nt][3] = __expf((sfrag[mt][nt][3] - mn1) * SC);
                s0s += sfrag[mt][nt][0] + sfrag[mt][nt][1];
                s1s += sfrag[mt][nt][2] + sfrag[mt][nt][3];
            }
            s0s += __shfl_xor_sync(0xffffffffu, s0s, 1);
            s0s += __shfl_xor_sync(0xffffffffu, s0s, 2);
            s1s += __shfl_xor_sync(0xffffffffu, s1s, 1);
            s1s += __shfl_xor_sync(0xffffffffu, s1s, 2);
            lrow[mt][0] += s0s;
            lrow[mt][1] += s1s;
            mrow[mt][0] = mn0;
            mrow[mt][1] = mn1;
        }

        #pragma unroll
        for (int ks = 0; ks < 4; ks++) {
            uint32_t ap[2][4];
            #pragma unroll
            for (int mt = 0; mt < 2; mt++) {
                ap[mt][0] = h2_u32(__floats2half2_rn(sfrag[mt][2 * ks][0],     sfrag[mt][2 * ks][1]));
                ap[mt][1] = h2_u32(__floats2half2_rn(sfrag[mt][2 * ks][2],     sfrag[mt][2 * ks][3]));
                ap[mt][2] = h2_u32(__floats2half2_rn(sfrag[mt][2 * ks + 1][0], sfrag[mt][2 * ks + 1][1]));
                ap[mt][3] = h2_u32(__floats2half2_rn(sfrag[mt][2 * ks + 1][2], sfrag[mt][2 * ks + 1][3]));
            }
            uint32_t bv[8][2];
            #pragma unroll
            for (int np = 0; np < 4; np++) {
                uint32_t d[4];
                ldm_x4_t(d, vsb[cur] + vToff +
                            (uint32_t)((ks * 16 * VS_LDH + np * 16) * 2));
                bv[np * 2][0]     = d[0]; bv[np * 2][1]     = d[1];
                bv[np * 2 + 1][0] = d[2]; bv[np * 2 + 1][1] = d[3];
            }
            #pragma unroll
            for (int mt = 0; mt < 2; mt++)
                #pragma unroll
                for (int nt = 0; nt < 8; nt++)
                    mma_f16(ofrag[mt][nt], ap[mt], bv[nt]);
        }
        __syncthreads();
    }

    #pragma unroll
    for (int mt = 0; mt < 2; mt++) {
        const int rowA = t0 + wr + mt * 16 + gr;
        const int rowB = rowA + 8;
        const float il0 = 1.0f / lrow[mt][0];
        const float il1 = 1.0f / lrow[mt][1];
        #pragma unroll
        for (int nt = 0; nt < 8; nt++) {
            const int col = hq * HEAD_DIM + nt * 8 + 2 * gc;
            *reinterpret_cast<__half2*>(o + (long)(b * SEQ + rowA) * D_MODEL + col) =
                __floats2half2_rn(ofrag[mt][nt][0] * il0, ofrag[mt][nt][1] * il0);
            *reinterpret_cast<__half2*>(o + (long)(b * SEQ + rowB) * D_MODEL + col) =
                __floats2half2_rn(ofrag[mt][nt][2] * il1, ofrag[mt][nt][3] * il1);
        }
    }
}

// ---------------------------------------------------------------------------
// Transpose to half
// ---------------------------------------------------------------------------
__global__ void transpose_h(const float* __restrict__ in,
                            __half* __restrict__ out, int R, int C) {
    __shared__ float t[32][33];
    const int c0 = blockIdx.x << 5, r0 = blockIdx.y << 5;
    #pragma unroll
    for (int dy = 0; dy < 32; dy += 8) {
        t[threadIdx.y + dy][threadIdx.x] =
            in[(long)(r0 + threadIdx.y + dy) * C + c0 + threadIdx.x];
    }
    __syncthreads();
    #pragma unroll
    for (int dy = 0; dy < 32; dy += 8) {
        out[(long)(c0 + threadIdx.y + dy) * R + r0 + threadIdx.x] =
            __float2half_rn(t[threadIdx.x][threadIdx.y + dy]);
    }
}

// ---------------------------------------------------------------------------
// RMSNorm: fp32 in, half out
// ---------------------------------------------------------------------------
__global__ void rmsnorm_h(const float* __restrict__ x,
                          const float* __restrict__ g,
                          __half* __restrict__ out) {
    const int row = blockIdx.x;
    const int tid = threadIdx.x;
    const float* xr = x + (long)row * D_MODEL;
    float4 v = *reinterpret_cast<const float4*>(xr + tid * 4);
    float s = v.x * v.x + v.y * v.y + v.z * v.z + v.w * v.w;

    #pragma unroll
    for (int off = 16; off > 0; off >>= 1)
        s += __shfl_xor_sync(0xffffffffu, s, off);

    __shared__ float red[8];
    if ((tid & 31) == 0) red[tid >> 5] = s;
    __syncthreads();
    float total;
    {
        float t = (tid < 8) ? red[tid] : 0.f;
        #pragma unroll
        for (int off = 4; off > 0; off >>= 1)
            t += __shfl_xor_sync(0xffffffffu, t, off);
        __shared__ float bc;
        if (tid == 0) bc = t;
        __syncthreads();
        total = bc;
    }
    float inv = rsqrtf(total * (1.0f / D_MODEL) + 1e-6f);
    float4 gv = *reinterpret_cast<const float4*>(g + tid * 4);
    uint2 pk;
    pk.x = h2_u32(__floats2half2_rn(v.x * inv * gv.x, v.y * inv * gv.y));
    pk.y = h2_u32(__floats2half2_rn(v.z * inv * gv.z, v.w * inv * gv.w));
    *reinterpret_cast<uint2*>(out + (long)row * D_MODEL + tid * 4) = pk;
}

// ---------------------------------------------------------------------------
// RoPE table: tab[t][j] = (cos, sin) of t * 10000^(-j/32)
// ---------------------------------------------------------------------------
__global__ void rope_tab_fill(float2* __restrict__ tab) {
    const int t = blockIdx.x;
    const int j = threadIdx.x;
    float inv = (float)exp(-(double)j / 32.0 * 9.210340371976184);
    float fr = (float)t * inv;
    tab[t * 32 + j] = make_float2(cosf(fr), sinf(fr));
}

// ---------------------------------------------------------------------------
// Launch
// ---------------------------------------------------------------------------
extern "C" void kernel_launch(void* const* d_in, const int* in_sizes, int n_in,
                              void* d_out, int out_size) {
    const float* x  = (const float*)d_in[0];
    const float* g1 = (const float*)d_in[1];
    const float* g2 = (const float*)d_in[2];
    const float* wq = (const float*)d_in[3];
    const float* wk = (const float*)d_in[4];
    const float* wv = (const float*)d_in[5];
    const float* wo = (const float*)d_in[6];
    const float* w1 = (const float*)d_in[7];
    const float* w2 = (const float*)d_in[8];
    const float* w3 = (const float*)d_in[9];
    float* out = (float*)d_out;

    __half *h, *qh, *kh, *vh, *ao, *h2, *a, *a2;
    __half *wqkvT, *woT, *w1T, *w2T, *w3T;
    float2* ropeT;
    cudaGetSymbolAddress((void**)&h,   g_h);
    cudaGetSymbolAddress((void**)&qh,  g_qh);
    cudaGetSymbolAddress((void**)&kh,  g_kh);
    cudaGetSymbolAddress((void**)&vh,  g_vh);
    cudaGetSymbolAddress((void**)&ao,  g_ao);
    cudaGetSymbolAddress((void**)&h2,  g_h2);
    cudaGetSymbolAddress((void**)&a,   g_a);
    cudaGetSymbolAddress((void**)&a2,  g_a2);
    cudaGetSymbolAddress((void**)&ropeT, g_rope);
    cudaGetSymbolAddress((void**)&wqkvT, g_wqkvT);
    cudaGetSymbolAddress((void**)&woT, g_woT);
    cudaGetSymbolAddress((void**)&w1T, g_w1T);
    cudaGetSymbolAddress((void**)&w2T, g_w2T);
    cudaGetSymbolAddress((void**)&w3T, g_w3T);

    cudaFuncSetAttribute(hgemm, cudaFuncAttributeMaxDynamicSharedMemorySize,
                         GEMM_SMEM_BYTES);
    cudaFuncSetAttribute(attn_h, cudaFuncAttributeMaxDynamicSharedMemorySize,
                         ATTN_SMEM);

    dim3 tb(32, 8);
    transpose_h<<<dim3(D_MODEL / 32, D_MODEL / 32), tb>>>(wq, wqkvT, D_MODEL, D_MODEL);
    transpose_h<<<dim3((N_KV * HEAD_DIM) / 32, D_MODEL / 32), tb>>>(wk, wqkvT + 1024 * D_MODEL, D_MODEL, N_KV * HEAD_DIM);
    transpose_h<<<dim3((N_KV * HEAD_DIM) / 32, D_MODEL / 32), tb>>>(wv, wqkvT + 1536 * D_MODEL, D_MODEL, N_KV * HEAD_DIM);
    transpose_h<<<dim3(D_MODEL / 32, D_MODEL / 32), tb>>>(wo, woT, D_MODEL, D_MODEL);
    transpose_h<<<dim3(HIDDEN / 32, D_MODEL / 32), tb>>>(w1, w1T, D_MODEL, HIDDEN);
    transpose_h<<<dim3(HIDDEN / 32, D_MODEL / 32), tb>>>(w2, w2T, D_MODEL, HIDDEN);
    transpose_h<<<dim3(D_MODEL / 32, HIDDEN / 32), tb>>>(w3, w3T, HIDDEN, D_MODEL);
    rope_tab_fill<<<SEQ, 32>>>(ropeT);

    // 1. h = rmsnorm(x, g1)
    rmsnorm_h<<<BT, 256>>>(x, g1, h);

    // 2. fused qkv projection + RoPE + half conversion (no fp32 roundtrip)
    hgemm<<<dim3(QKV_N / 128, BT / 128), 128, GEMM_SMEM_BYTES>>>(
        h, wqkvT, nullptr, nullptr, BT, QKV_N, D_MODEL, EPI_ROPE,
        qh, kh, vh, ropeT);

    // 3. fp16 attention -> ao
    attn_h<<<dim3(SEQ / 128, BATCH * N_HEADS), 128, ATTN_SMEM>>>(qh, kh, vh, ao);

    // 4. out = ao @ wo + x
    hgemm<<<dim3(D_MODEL / 128, BT / 128), 128, GEMM_SMEM_BYTES>>>(
        ao, woT, x, out, BT, D_MODEL, D_MODEL, EPI_RES,
        nullptr, nullptr, nullptr, nullptr);

    // 5. h2 = rmsnorm(out, g2)
    rmsnorm_h<<<BT, 256>>>(out, g2, h2);

    // 6. a = h2 @ w1;  a2 = silu(a) * (h2 @ w2)
    hgemm<<<dim3(HIDDEN / 128, BT / 128), 128, GEMM_SMEM_BYTES>>>(
        h2, w1T, nullptr, a, BT, HIDDEN, D_MODEL, EPI_HALF,
        nullptr, nullptr, nullptr, nullptr);
    hgemm<<<dim3(HIDDEN / 128, BT / 128), 128, GEMM_SMEM_BYTES>>>(
        h2, w2T, a, a2, BT, HIDDEN, D_MODEL, EPI_SILU,
        nullptr, nullptr, nullptr, nullptr);

    // 7. out += a2 @ w3
    hgemm<<<dim3(D_MODEL / 128, BT / 128), 128, GEMM_SMEM_BYTES>>>(
        a2, w3T, out, out, BT, D_MODEL, HIDDEN, EPI_RES,
        nullptr, nullptr, nullptr, nullptr);
}

// round 12
// speedup vs baseline: 2.7680x; 1.0452x over previous
#include <cuda_runtime.h>
#include <cuda_fp16.h>
#include <math.h>
#include <stdint.h>

// ---------------------------------------------------------------------------
// Problem constants
// ---------------------------------------------------------------------------
#define D_MODEL   1024
#define N_HEADS   16
#define N_KV      8
#define HEAD_DIM  64
#define HIDDEN    4096
#define BATCH     4
#define SEQ       2048
#define BT        (BATCH * SEQ)
#define QKV_N     2048

// ---------------------------------------------------------------------------
// Scratch (device globals)
// ---------------------------------------------------------------------------
__device__ __half g_h  [BT * D_MODEL];
__device__ __half g_qh [BT * D_MODEL];
__device__ __half g_kh [BT * N_KV * HEAD_DIM];
__device__ __half g_vh [BT * N_KV * HEAD_DIM];
__device__ __half g_ao [BT * D_MODEL];
__device__ __half g_h2 [BT * D_MODEL];
__device__ __half g_a2 [BT * HIDDEN];
__device__ float2 g_rope[SEQ * 32];

__device__ __half g_wqkvT[QKV_N * D_MODEL];
__device__ __half g_woT [D_MODEL * D_MODEL];
__device__ __half g_w12T[2 * HIDDEN * D_MODEL];  // interleaved w1/w2 rows
__device__ __half g_w3T [D_MODEL * HIDDEN];

// ---------------------------------------------------------------------------
// Helpers
// ---------------------------------------------------------------------------
__device__ __forceinline__ void mma_f16(float* c, const uint32_t* a, const uint32_t* b) {
    asm volatile(
        "mma.sync.aligned.m16n8k16.row.col.f32.f16.f16.f32 "
        "{%0,%1,%2,%3}, {%4,%5,%6,%7}, {%8,%9}, {%0,%1,%2,%3};\n"
        : "+f"(c[0]), "+f"(c[1]), "+f"(c[2]), "+f"(c[3])
        : "r"(a[0]), "r"(a[1]), "r"(a[2]), "r"(a[3]), "r"(b[0]), "r"(b[1]));
}
__device__ __forceinline__ void ldm_x4(uint32_t* d, uint32_t saddr) {
    asm volatile(
        "ldmatrix.sync.aligned.m8n8.x4.shared.b16 {%0,%1,%2,%3}, [%4];"
        : "=r"(d[0]), "=r"(d[1]), "=r"(d[2]), "=r"(d[3]) : "r"(saddr));
}
__device__ __forceinline__ void ldm_x4_t(uint32_t* d, uint32_t saddr) {
    asm volatile(
        "ldmatrix.sync.aligned.m8n8.x4.trans.shared.b16 {%0,%1,%2,%3}, [%4];"
        : "=r"(d[0]), "=r"(d[1]), "=r"(d[2]), "=r"(d[3]) : "r"(saddr));
}
__device__ __forceinline__ uint32_t cvta_s(const void* p) {
    return (uint32_t)__cvta_generic_to_shared(p);
}
__device__ __forceinline__ void cp16(uint32_t dst, const void* src) {
    asm volatile(
        "{ .reg .u64 g; cvta.to.global.u64 g, %1; "
        "cp.async.cg.shared.global [%0], [g], 16; }"
        :: "r"(dst), "l"(src) : "memory");
}
#define CP_COMMIT() asm volatile("cp.async.commit_group;\n" ::: "memory")
#define CP_WAIT1()  asm volatile("cp.async.wait_group 1;\n" ::: "memory")
#define CP_WAIT0()  asm volatile("cp.async.wait_group 0;\n" ::: "memory")

__device__ __forceinline__ uint32_t h2_u32(__half2 h) {
    uint32_t u;
    *reinterpret_cast<__half2*>(&u) = h;
    return u;
}

#define EPI_RES    1
#define EPI_HALF   2
#define EPI_ROPE   4
#define EPI_SWIGLU 5   // interleaved (a,b) pairs -> silu(a)*b half, N/2 cols

// ---------------------------------------------------------------------------
// fp16 tensor-core GEMM; mainloop unchanged (passing since R8)
// ---------------------------------------------------------------------------
#define BKH   32
#define LDH   40
#define STG_H (128 * LDH)
#define GEMM_SMEM_BYTES (6 * STG_H * 2)

__global__ void __launch_bounds__(128, 2)
hgemm(const __half* __restrict__ A, const __half* __restrict__ Bt,
      const void* __restrict__ Rv, void* __restrict__ Cv,
      int M, int N, int K, int epi,
      __half* __restrict__ q_out, __half* __restrict__ k_out,
      __half* __restrict__ v_out, const float2* __restrict__ rope_tab) {
    extern __shared__ __half smh[];
    __half* Abuf[3] = { smh, smh + 2 * STG_H, smh + 4 * STG_H };
    __half* Bbuf[3] = { smh + STG_H, smh + 3 * STG_H, smh + 5 * STG_H };

    const int tid  = threadIdx.x;
    const int wid  = tid >> 5;
    const int lane = tid & 31;
    const int wm   = wid >> 1;
    const int wn   = wid & 1;
    const int gr   = lane >> 2;
    const int gc   = lane & 3;
    const int m0 = blockIdx.y << 7;
    const int n0 = blockIdx.x << 7;

    const int lr = tid >> 2;
    const int lc = (tid & 3) << 3;
    const __half* Ag = A  + (long)(m0 + lr) * K + lc;
    const __half* Bg = Bt + (long)(n0 + lr) * K + lc;

    uint32_t sA[3], sB[3], sAb[3], sBb[3];
    #pragma unroll
    for (int s = 0; s < 3; s++) {
        sAb[s] = cvta_s(Abuf[s]);
        sBb[s] = cvta_s(Bbuf[s]);
        sA[s] = cvta_s(&Abuf[s][lr * LDH + lc]);
        sB[s] = cvta_s(&Bbuf[s][lr * LDH + lc]);
    }
    const uint32_t rowstep = 32 * LDH * 2;

    const int l7  = lane & 7;
    const int sel = lane >> 3;
    const uint32_t aOff = (uint32_t)(((wm * 64 + l7 + (sel & 1) * 8) * LDH + (sel >> 1) * 8) * 2);
    const uint32_t bOff = (uint32_t)(((wn * 64 + l7 + (sel >> 1) * 8) * LDH + (sel & 1) * 8) * 2);

    const int NC = K / BKH;

    float acc[4][8][4];
    #pragma unroll
    for (int i = 0; i < 4; i++)
        #pragma unroll
        for (int j = 0; j < 8; j++)
            #pragma unroll
            for (int q = 0; q < 4; q++) acc[i][j][q] = 0.f;

    #pragma unroll
    for (int c0i = 0; c0i < 2; c0i++) {
        const long ko = (long)c0i * BKH;
        #pragma unroll
        for (int p = 0; p < 4; p++) {
            cp16(sA[c0i] + p * rowstep, Ag + (long)(p * 32) * K + ko);
            cp16(sB[c0i] + p * rowstep, Bg + (long)(p * 32) * K + ko);
        }
        CP_COMMIT();
    }

    for (int i = 0; i < NC; i++) {
        if (i < NC - 1) CP_WAIT1(); else CP_WAIT0();
        __syncthreads();

        if (i + 2 < NC) {
            const int s2 = (i + 2) % 3;
            const long ko = (long)(i + 2) * BKH;
            #pragma unroll
            for (int p = 0; p < 4; p++) {
                cp16(sA[s2] + p * rowstep, Ag + (long)(p * 32) * K + ko);
                cp16(sB[s2] + p * rowstep, Bg + (long)(p * 32) * K + ko);
            }
            CP_COMMIT();
        }

        const int cur = i % 3;
        const uint32_t aBase = sAb[cur] + aOff;
        const uint32_t bBase = sBb[cur] + bOff;

        #pragma unroll
        for (int ks = 0; ks < 2; ks++) {
            const uint32_t kb = (uint32_t)(ks * 16 * 2);
            uint32_t af[4][4], bf[8][2];
            #pragma unroll
            for (int mt = 0; mt < 4; mt++)
                ldm_x4(af[mt], aBase + (uint32_t)(mt * 16 * LDH * 2) + kb);
            #pragma unroll
            for (int np = 0; np < 4; np++) {
                uint32_t d[4];
                ldm_x4(d, bBase + (uint32_t)(np * 16 * LDH * 2) + kb);
                bf[np * 2][0]     = d[0]; bf[np * 2][1]     = d[1];
                bf[np * 2 + 1][0] = d[2]; bf[np * 2 + 1][1] = d[3];
            }
            #pragma unroll
            for (int mt = 0; mt < 4; mt++)
                #pragma unroll
                for (int nt = 0; nt < 8; nt++)
                    mma_f16(acc[mt][nt], af[mt], bf[nt]);
        }
    }
    __syncthreads();

    // ---------------- epilogues ----------------
    if (epi == EPI_ROPE) {
        const int head = (n0 + wn * 64) >> 6;
        #pragma unroll
        for (int mt = 0; mt < 4; mt++) {
            const int rowA = m0 + wm * 64 + mt * 16 + gr;
            const int rowB = rowA + 8;
            const int tA = rowA & (SEQ - 1);
            const int tB = rowB & (SEQ - 1);
            if (head < 24) {
                __half* dstA;
                long stride;
                if (head < 16) {
                    dstA = q_out + (long)rowA * D_MODEL + head * HEAD_DIM;
                    stride = D_MODEL;
                } else {
                    dstA = k_out + (long)rowA * (N_KV * HEAD_DIM) + (head - 16) * HEAD_DIM;
                    stride = N_KV * HEAD_DIM;
                }
                __half* dstB = dstA + 8 * stride;
                #pragma unroll
                for (int nt = 0; nt < 4; nt++) {
                    const int j0 = nt * 8 + gc * 2;
                    const float2 cA0 = rope_tab[tA * 32 + j0];
                    const float2 cA1 = rope_tab[tA * 32 + j0 + 1];
                    const float2 cB0 = rope_tab[tB * 32 + j0];
                    const float2 cB1 = rope_tab[tB * 32 + j0 + 1];
                    const float x1a0 = acc[mt][nt][0],     x1a1 = acc[mt][nt][1];
                    const float x1b0 = acc[mt][nt][2],     x1b1 = acc[mt][nt][3];
                    const float x2a0 = acc[mt][nt + 4][0], x2a1 = acc[mt][nt + 4][1];
                    const float x2b0 = acc[mt][nt + 4][2], x2b1 = acc[mt][nt + 4][3];
                    *reinterpret_cast<__half2*>(dstA + j0) =
                        __floats2half2_rn(x1a0 * cA0.x - x2a0 * cA0.y,
                                          x1a1 * cA1.x - x2a1 * cA1.y);
                    *reinterpret_cast<__half2*>(dstA + j0 + 32) =
                        __floats2half2_rn(x2a0 * cA0.x + x1a0 * cA0.y,
                                          x2a1 * cA1.x + x1a1 * cA1.y);
                    *reinterpret_cast<__half2*>(dstB + j0) =
                        __floats2half2_rn(x1b0 * cB0.x - x2b0 * cB0.y,
                                          x1b1 * cB1.x - x2b1 * cB1.y);
                    *reinterpret_cast<__half2*>(dstB + j0 + 32) =
                        __floats2half2_rn(x2b0 * cB0.x + x1b0 * cB0.y,
                                          x2b1 * cB1.x + x1b1 * cB1.y);
                }
            } else {
                __half* dstA = v_out + (long)rowA * (N_KV * HEAD_DIM) + (head - 24) * HEAD_DIM;
                __half* dstB = dstA + 8 * (N_KV * HEAD_DIM);
                #pragma unroll
                for (int nt = 0; nt < 8; nt++) {
                    const int c = nt * 8 + gc * 2;
                    *reinterpret_cast<__half2*>(dstA + c) =
                        __floats2half2_rn(acc[mt][nt][0], acc[mt][nt][1]);
                    *reinterpret_cast<__half2*>(dstB + c) =
                        __floats2half2_rn(acc[mt][nt][2], acc[mt][nt][3]);
                }
            }
        }
        return;
    }

    if (epi == EPI_SWIGLU) {
        // cols interleaved (w1_j, w2_j): each acc float2 = (a_j, b_j)
        __half* C = (__half*)Cv;
        const int NH = N >> 1;
        #pragma unroll
        for (int mt = 0; mt < 4; mt++) {
            #pragma unroll
            for (int nt = 0; nt < 8; nt++) {
                const int row = m0 + wm * 64 + mt * 16 + gr;
                const int jcol = ((n0 + wn * 64 + nt * 8) >> 1) + gc;
                const float aA = acc[mt][nt][0], bA = acc[mt][nt][1];
                const float aB = acc[mt][nt][2], bB = acc[mt][nt][3];
                C[(long)row * NH + jcol] =
                    __float2half_rn(aA / (1.0f + __expf(-aA)) * bA);
                C[(long)(row + 8) * NH + jcol] =
                    __float2half_rn(aB / (1.0f + __expf(-aB)) * bB);
            }
        }
        return;
    }

    #pragma unroll
    for (int mt = 0; mt < 4; mt++) {
        #pragma unroll
        for (int nt = 0; nt < 8; nt++) {
            const int row = m0 + wm * 64 + mt * 16 + gr;
            const int col = n0 + wn * 64 + nt * 8 + gc * 2;
            const long offA = (long)row * N + col;
            const long offB = (long)(row + 8) * N + col;
            float2 lo = make_float2(acc[mt][nt][0], acc[mt][nt][1]);
            float2 hi = make_float2(acc[mt][nt][2], acc[mt][nt][3]);
            if (epi == EPI_RES) {
                const float* R = (const float*)Rv;
                float2 r0 = *reinterpret_cast<const float2*>(R + offA);
                float2 r1 = *reinterpret_cast<const float2*>(R + offB);
                lo.x += r0.x; lo.y += r0.y;
                hi.x += r1.x; hi.y += r1.y;
                *reinterpret_cast<float2*>((float*)Cv + offA) = lo;
                *reinterpret_cast<float2*>((float*)Cv + offB) = hi;
            } else {  // EPI_HALF
                *reinterpret_cast<__half2*>((__half*)Cv + offA) = __floats2half2_rn(lo.x, lo.y);
                *reinterpret_cast<__half2*>((__half*)Cv + offB) = __floats2half2_rn(hi.x, hi.y);
            }
        }
    }
}

// ---------------------------------------------------------------------------
// fp16 flash attention, causal GQA (unchanged from R10/R11, passing)
// ---------------------------------------------------------------------------
#define QS_LDH 72
#define KS_LDH 72
#define VS_LDH 72
#define ATTN_SMEM ((128 * QS_LDH + 2 * 64 * KS_LDH + 2 * 64 * VS_LDH) * 2)

__global__ void __launch_bounds__(128, 2)
attn_h(const __half* __restrict__ qh, const __half* __restrict__ kh,
       const __half* __restrict__ vh, __half* __restrict__ o) {
    extern __shared__ __half smh[];
    __half* Qs = smh;
    __half* Kb[2] = { smh + 128 * QS_LDH, smh + 128 * QS_LDH + 64 * KS_LDH };
    __half* Vb[2] = { Kb[1] + 64 * KS_LDH, Kb[1] + 64 * KS_LDH + 64 * VS_LDH };

    const int tid  = threadIdx.x;
    const int warp = tid >> 5;
    const int lane = tid & 31;
    const int gr = lane >> 2;
    const int gc = lane & 3;
    const int wr = warp << 5;

    const int t0  = blockIdx.x << 7;
    const int bh  = blockIdx.y;
    const int b   = bh >> 4;
    const int hq  = bh & 15;
    const int kvh = hq >> 1;

    const uint32_t qsb = cvta_s(Qs);
    uint32_t ksb[2] = { cvta_s(Kb[0]), cvta_s(Kb[1]) };
    uint32_t vsb[2] = { cvta_s(Vb[0]), cvta_s(Vb[1]) };

    const int l7  = lane & 7;
    const int sel = lane >> 3;
    const uint32_t aQoff = (uint32_t)(((wr + l7 + (sel & 1) * 8) * QS_LDH + (sel >> 1) * 8) * 2);
    const uint32_t bKoff = (uint32_t)(((l7 + (sel >> 1) * 8) * KS_LDH + (sel & 1) * 8) * 2);
    const uint32_t vToff = (uint32_t)((((sel & 1) * 8 + l7) * VS_LDH + (sel >> 1) * 8) * 2);

    const int ldr = tid >> 3;
    const int ldc = (tid & 7) << 3;

    {
        #pragma unroll
        for (int p = 0; p < 8; p++) {
            const int row = ldr + p * 16;
            cp16(qsb + (uint32_t)((row * QS_LDH + ldc) * 2),
                 qh + (long)(b * SEQ + t0 + row) * D_MODEL + hq * HEAD_DIM + ldc);
        }
    }
    {
        #pragma unroll
        for (int p = 0; p < 4; p++) {
            const int row = ldr + p * 16;
            const long base = (long)(b * SEQ + row) * (N_KV * HEAD_DIM) + kvh * HEAD_DIM + ldc;
            cp16(ksb[0] + (uint32_t)((row * KS_LDH + ldc) * 2), kh + base);
            cp16(vsb[0] + (uint32_t)((row * VS_LDH + ldc) * 2), vh + base);
        }
        CP_COMMIT();
    }

    float ofrag[2][8][4];
    #pragma unroll
    for (int mt = 0; mt < 2; mt++)
        #pragma unroll
        for (int nt = 0; nt < 8; nt++)
            #pragma unroll
            for (int r = 0; r < 4; r++) ofrag[mt][nt][r] = 0.f;

    float mrow[2][2] = {{-1e30f, -1e30f}, {-1e30f, -1e30f}};
    float lrow[2][2] = {{0.f, 0.f}, {0.f, 0.f}};
    const float SC = 0.125f;

    const int ntiles = (t0 >> 6) + 2;
    for (int it = 0; it < ntiles; it++) {
        const int s0 = it << 6;
        const int cur = it & 1;

        if (it + 1 < ntiles) {
            const int nxt = cur ^ 1;
            const long roff = (long)((it + 1) << 6) * (N_KV * HEAD_DIM);
            #pragma unroll
            for (int p = 0; p < 4; p++) {
                const int row = ldr + p * 16;
                const long base = (long)(b * SEQ + row) * (N_KV * HEAD_DIM) + kvh * HEAD_DIM + ldc + roff;
                cp16(ksb[nxt] + (uint32_t)((row * KS_LDH + ldc) * 2), kh + base);
                cp16(vsb[nxt] + (uint32_t)((row * VS_LDH + ldc) * 2), vh + base);
            }
            CP_COMMIT();
            CP_WAIT1();
        } else {
            CP_WAIT0();
        }
        __syncthreads();

        float sfrag[2][8][4];
        #pragma unroll
        for (int mt = 0; mt < 2; mt++)
            #pragma unroll
            for (int nt = 0; nt < 8; nt++)
                #pragma unroll
                for (int r = 0; r < 4; r++) sfrag[mt][nt][r] = 0.f;

        #pragma unroll
        for (int ks = 0; ks < 4; ks++) {
            const uint32_t kb = (uint32_t)(ks * 16 * 2);
            uint32_t aq[2][4], bk[8][2];
            #pragma unroll
            for (int mt = 0; mt < 2; mt++)
                ldm_x4(aq[mt], qsb + aQoff + (uint32_t)(mt * 16 * QS_LDH * 2) + kb);
            #pragma unroll
            for (int np = 0; np < 4; np++) {
                uint32_t d[4];
                ldm_x4(d, ksb[cur] + bKoff + (uint32_t)(np * 16 * KS_LDH * 2) + kb);
                bk[np * 2][0]     = d[0]; bk[np * 2][1]     = d[1];
                bk[np * 2 + 1][0] = d[2]; bk[np * 2 + 1][1] = d[3];
            }
            #pragma unroll
            for (int mt = 0; mt < 2; mt++)
                #pragma unroll
                for (int nt = 0; nt < 8; nt++)
                    mma_f16(sfrag[mt][nt], aq[mt], bk[nt]);
        }

        if (it >= ntiles - 2) {
            #pragma unroll
            for (int mt = 0; mt < 2; mt++) {
                const int rA = t0 + wr + mt * 16 + gr;
                const int rB = rA + 8;
                #pragma unroll
                for (int nt = 0; nt < 8; nt++) {
                    const int cb = s0 + nt * 8 + 2 * gc;
                    if (cb     > rA) sfrag[mt][nt][0] = -1e30f;
                    if (cb + 1 > rA) sfrag[mt][nt][1] = -1e30f;
                    if (cb     > rB) sfrag[mt][nt][2] = -1e30f;
                    if (cb + 1 > rB) sfrag[mt][nt][3] = -1e30f;
                }
            }
        }

        #pragma unroll
        for (int mt = 0; mt < 2; mt++) {
            float r0 = -1e30f, r1 = -1e30f;
            #pragma unroll
            for (int nt = 0; nt < 8; nt++) {
                r0 = fmaxf(r0, fmaxf(sfrag[mt][nt][0], sfrag[mt][nt][1]));
                r1 = fmaxf(r1, fmaxf(sfrag[mt][nt][2], sfrag[mt][nt][3]));
            }
            r0 = fmaxf(r0, __shfl_xor_sync(0xffffffffu, r0, 1));
            r0 = fmaxf(r0, __shfl_xor_sync(0xffffffffu, r0, 2));
            r1 = fmaxf(r1, __shfl_xor_sync(0xffffffffu, r1, 1));
            r1 = fmaxf(r1, __shfl_xor_sync(0xffffffffu, r1, 2));

            const float mn0 = fmaxf(mrow[mt][0], r0);
            const float mn1 = fmaxf(mrow[mt][1], r1);
            const float c0 = __expf((mrow[mt][0] - mn0) * SC);
            const float c1 = __expf((mrow[mt][1] - mn1) * SC);
            lrow[mt][0] *= c0;
            lrow[mt][1] *= c1;
            #pragma unroll
            for (int nt = 0; nt < 8; nt++) {
                ofrag[mt][nt][0] *= c0; ofrag[mt][nt][1] *= c0;
                ofrag[mt][nt][2] *= c1; ofrag[mt][nt][3] *= c1;
            }
            float s0s = 0.f, s1s = 0.f;
            #pragma unroll
            for (int nt = 0; nt < 8; nt++) {
                sfrag[mt][nt][0] = __expf((sfrag[mt][nt][0] - mn0) * SC);
                sfrag[mt][nt][1] = __expf((sfrag[mt][nt][1] - mn0) * SC);
                sfrag[mt][nt][2] = __expf((sfrag[mt][nt][2] - mn1) * SC);
                sfrag[mt][nt][3] = __expf((sfrag[mt][nt][3] - mn1) * SC);
                s0s += sfrag[mt][nt][0] + sfrag[mt][nt][1];
                s1s += sfrag[mt][nt][2] + sfrag[mt][nt][3];
            }
            s0s += __shfl_xor_sync(0xffffffffu, s0s, 1);
            s0s += __shfl_xor_sync(0xffffffffu, s0s, 2);
            s1s += __shfl_xor_sync(0xffffffffu, s1s, 1);
            s1s += __shfl_xor_sync(0xffffffffu, s1s, 2);
            lrow[mt][0] += s0s;
            lrow[mt][1] += s1s;
            mrow[mt][0] = mn0;
            mrow[mt][1] = mn1;
        }

        #pragma unroll
        for (int ks = 0; ks < 4; ks++) {
            uint32_t ap[2][4];
            #pragma unroll
            for (int mt = 0; mt < 2; mt++) {
                ap[mt][0] = h2_u32(__floats2half2_rn(sfrag[mt][2 * ks][0],     sfrag[mt][2 * ks][1]));
                ap[mt][1] = h2_u32(__floats2half2_rn(sfrag[mt][2 * ks][2],     sfrag[mt][2 * ks][3]));
                ap[mt][2] = h2_u32(__floats2half2_rn(sfrag[mt][2 * ks + 1][0], sfrag[mt][2 * ks + 1][1]));
                ap[mt][3] = h2_u32(__floats2half2_rn(sfrag[mt][2 * ks + 1][2], sfrag[mt][2 * ks + 1][3]));
            }
            uint32_t bv[8][2];
            #pragma unroll
            for (int np = 0; np < 4; np++) {
                uint32_t d[4];
                ldm_x4_t(d, vsb[cur] + vToff +
                            (uint32_t)((ks * 16 * VS_LDH + np * 16) * 2));
                bv[np * 2][0]     = d[0]; bv[np * 2][1]     = d[1];
                bv[np * 2 + 1][0] = d[2]; bv[np * 2 + 1][1] = d[3];
            }
            #pragma unroll
            for (int mt = 0; mt < 2; mt++)
                #pragma unroll
                for (int nt = 0; nt < 8; nt++)
                    mma_f16(ofrag[mt][nt], ap[mt], bv[nt]);
        }
        __syncthreads();
    }

    #pragma unroll
    for (int mt = 0; mt < 2; mt++) {
        const int rowA = t0 + wr + mt * 16 + gr;
        const int rowB = rowA + 8;
        const float il0 = 1.0f / lrow[mt][0];
        const float il1 = 1.0f / lrow[mt][1];
        #pragma unroll
        for (int nt = 0; nt < 8; nt++) {
            const int col = hq * HEAD_DIM + nt * 8 + 2 * gc;
            *reinterpret_cast<__half2*>(o + (long)(b * SEQ + rowA) * D_MODEL + col) =
                __floats2half2_rn(ofrag[mt][nt][0] * il0, ofrag[mt][nt][1] * il0);
            *reinterpret_cast<__half2*>(o + (long)(b * SEQ + rowB) * D_MODEL + col) =
                __floats2half2_rn(ofrag[mt][nt][2] * il1, ofrag[mt][nt][3] * il1);
        }
    }
}

// ---------------------------------------------------------------------------
// Transpose to half: out[(c*stride + roff)*R + r] = in[r*C + c]
// ---------------------------------------------------------------------------
__global__ void transpose_h(const float* __restrict__ in,
                            __half* __restrict__ out, int R, int C,
                            int stride, int roff) {
    __shared__ float t[32][33];
    const int c0 = blockIdx.x << 5, r0 = blockIdx.y << 5;
    #pragma unroll
    for (int dy = 0; dy < 32; dy += 8) {
        t[threadIdx.y + dy][threadIdx.x] =
            in[(long)(r0 + threadIdx.y + dy) * C + c0 + threadIdx.x];
    }
    __syncthreads();
    #pragma unroll
    for (int dy = 0; dy < 32; dy += 8) {
        out[(long)((c0 + threadIdx.y + dy) * stride + roff) * R + r0 + threadIdx.x] =
            __float2half_rn(t[threadIdx.x][threadIdx.y + dy]);
    }
}

// ---------------------------------------------------------------------------
// RMSNorm: fp32 in, half out
// ---------------------------------------------------------------------------
__global__ void rmsnorm_h(const float* __restrict__ x,
                          const float* __restrict__ g,
                          __half* __restrict__ out) {
    const int row = blockIdx.x;
    const int tid = threadIdx.x;
    const float* xr = x + (long)row * D_MODEL;
    float4 v = *reinterpret_cast<const float4*>(xr + tid * 4);
    float s = v.x * v.x + v.y * v.y + v.z * v.z + v.w * v.w;

    #pragma unroll
    for (int off = 16; off > 0; off >>= 1)
        s += __shfl_xor_sync(0xffffffffu, s, off);

    __shared__ float red[8];
    if ((tid & 31) == 0) red[tid >> 5] = s;
    __syncthreads();
    float total;
    {
        float t = (tid < 8) ? red[tid] : 0.f;
        #pragma unroll
        for (int off = 4; off > 0; off >>= 1)
            t += __shfl_xor_sync(0xffffffffu, t, off);
        __shared__ float bc;
        if (tid == 0) bc = t;
        __syncthreads();
        total = bc;
    }
    float inv = rsqrtf(total * (1.0f / D_MODEL) + 1e-6f);
    float4 gv = *reinterpret_cast<const float4*>(g + tid * 4);
    uint2 pk;
    pk.x = h2_u32(__floats2half2_rn(v.x * inv * gv.x, v.y * inv * gv.y));
    pk.y = h2_u32(__floats2half2_rn(v.z * inv * gv.z, v.w * inv * gv.w));
    *reinterpret_cast<uint2*>(out + (long)row * D_MODEL + tid * 4) = pk;
}

// ---------------------------------------------------------------------------
// RoPE table
// ---------------------------------------------------------------------------
__global__ void rope_tab_fill(float2* __restrict__ tab) {
    const int t = blockIdx.x;
    const int j = threadIdx.x;
    float inv = (float)exp(-(double)j / 32.0 * 9.210340371976184);
    float fr = (float)t * inv;
    tab[t * 32 + j] = make_float2(cosf(fr), sinf(fr));
}

// ---------------------------------------------------------------------------
// Launch
// ---------------------------------------------------------------------------
extern "C" void kernel_launch(void* const* d_in, const int* in_sizes, int n_in,
                              void* d_out, int out_size) {
    const float* x  = (const float*)d_in[0];
    const float* g1 = (const float*)d_in[1];
    const float* g2 = (const float*)d_in[2];
    const float* wq = (const float*)d_in[3];
    const float* wk = (const float*)d_in[4];
    const float* wv = (const float*)d_in[5];
    const float* wo = (const float*)d_in[6];
    const float* w1 = (const float*)d_in[7];
    const float* w2 = (const float*)d_in[8];
    const float* w3 = (const float*)d_in[9];
    float* out = (float*)d_out;

    __half *h, *qh, *kh, *vh, *ao, *h2, *a2;
    __half *wqkvT, *woT, *w12T, *w3T;
    float2* ropeT;
    cudaGetSymbolAddress((void**)&h,   g_h);
    cudaGetSymbolAddress((void**)&qh,  g_qh);
    cudaGetSymbolAddress((void**)&kh,  g_kh);
    cudaGetSymbolAddress((void**)&vh,  g_vh);
    cudaGetSymbolAddress((void**)&ao,  g_ao);
    cudaGetSymbolAddress((void**)&h2,  g_h2);
    cudaGetSymbolAddress((void**)&a2,  g_a2);
    cudaGetSymbolAddress((void**)&ropeT, g_rope);
    cudaGetSymbolAddress((void**)&wqkvT, g_wqkvT);
    cudaGetSymbolAddress((void**)&woT,  g_woT);
    cudaGetSymbolAddress((void**)&w12T, g_w12T);
    cudaGetSymbolAddress((void**)&w3T,  g_w3T);

    cudaFuncSetAttribute(hgemm, cudaFuncAttributeMaxDynamicSharedMemorySize,
                         GEMM_SMEM_BYTES);
    cudaFuncSetAttribute(attn_h, cudaFuncAttributeMaxDynamicSharedMemorySize,
                         ATTN_SMEM);

    dim3 tb(32, 8);
    transpose_h<<<dim3(D_MODEL / 32, D_MODEL / 32), tb>>>(wq, wqkvT, D_MODEL, D_MODEL, 1, 0);
    transpose_h<<<dim3((N_KV * HEAD_DIM) / 32, D_MODEL / 32), tb>>>(wk, wqkvT + 1024 * D_MODEL, D_MODEL, N_KV * HEAD_DIM, 1, 0);
    transpose_h<<<dim3((N_KV * HEAD_DIM) / 32, D_MODEL / 32), tb>>>(wv, wqkvT + 1536 * D_MODEL, D_MODEL, N_KV * HEAD_DIM, 1, 0);
    transpose_h<<<dim3(D_MODEL / 32, D_MODEL / 32), tb>>>(wo, woT, D_MODEL, D_MODEL, 1, 0);
    // interleave w1/w2: row 2j <- w1 col j, row 2j+1 <- w2 col j
    transpose_h<<<dim3(HIDDEN / 32, D_MODEL / 32), tb>>>(w1, w12T, D_MODEL, HIDDEN, 2, 0);
    transpose_h<<<dim3(HIDDEN / 32, D_MODEL / 32), tb>>>(w2, w12T, D_MODEL, HIDDEN, 2, 1);
    transpose_h<<<dim3(D_MODEL / 32, HIDDEN / 32), tb>>>(w3, w3T, HIDDEN, D_MODEL, 1, 0);
    rope_tab_fill<<<SEQ, 32>>>(ropeT);

    // 1. h = rmsnorm(x, g1)
    rmsnorm_h<<<BT, 256>>>(x, g1, h);

    // 2. fused qkv projection + RoPE + half conversion
    hgemm<<<dim3(QKV_N / 128, BT / 128), 128, GEMM_SMEM_BYTES>>>(
        h, wqkvT, nullptr, nullptr, BT, QKV_N, D_MODEL, EPI_ROPE,
        qh, kh, vh, ropeT);

    // 3. fp16 attention -> ao
    attn_h<<<dim3(SEQ / 128, BATCH * N_HEADS), 128, ATTN_SMEM>>>(qh, kh, vh, ao);

    // 4. out = ao @ wo + x
    hgemm<<<dim3(D_MODEL / 128, BT / 128), 128, GEMM_SMEM_BYTES>>>(
        ao, woT, x, out, BT, D_MODEL, D_MODEL, EPI_RES,
        nullptr, nullptr, nullptr, nullptr);

    // 5. h2 = rmsnorm(out, g2)
    rmsnorm_h<<<BT, 256>>>(out, g2, h2);

    // 6. fused FFN-up: a2 = silu(h2 @ w1) * (h2 @ w2), one N=8192 GEMM
    hgemm<<<dim3((2 * HIDDEN) / 128, BT / 128), 128, GEMM_SMEM_BYTES>>>(
        h2, w12T, nullptr, a2, BT, 2 * HIDDEN, D_MODEL, EPI_SWIGLU,
        nullptr, nullptr, nullptr, nullptr);

    // 7. out += a2 @ w3
    hgemm<<<dim3(D_MODEL / 128, BT / 128), 128, GEMM_SMEM_BYTES>>>(
        a2, w3T, out, out, BT, D_MODEL, HIDDEN, EPI_RES,
        nullptr, nullptr, nullptr, nullptr);
}